// round 1
// baseline (speedup 1.0000x reference)
#include <cuda_runtime.h>
#include <cuda_bf16.h>
#include <math.h>

typedef unsigned long long ull;

// ---------------- scratch (device globals; no allocs allowed) ----------------
#define BATCH 64
#define LSEQ  2048
#define DMODEL 256
#define DU 1024
#define HHID 128
#define NTOK (BATCH*LSEQ)

__device__ float g_hev[(size_t)NTOK * DMODEL];   // 128MB token features
__device__ float g_WaT[DMODEL * DU];             // Wa transposed [d][u]
__device__ float g_cvec[HHID];                   // Ws1[:,D:]@vn + bs1
__device__ float g_aval[NTOK];                   // A_hat values
__device__ int   g_active[NTOK];                 // compacted local token ids per batch
__device__ int   g_count[BATCH];

// ---------------- f32x2 packed helpers ----------------
__device__ __forceinline__ ull pk2(float v) {
    ull r; asm("mov.b64 %0, {%1, %1};" : "=l"(r) : "f"(v)); return r;
}
__device__ __forceinline__ float2 unpk(ull v) {
    float2 r; asm("mov.b64 {%0, %1}, %2;" : "=f"(r.x), "=f"(r.y) : "l"(v)); return r;
}
__device__ __forceinline__ ull fma2(ull a, ull b, ull c) {
    ull d; asm("fma.rn.f32x2 %0, %1, %2, %3;" : "=l"(d) : "l"(a), "l"(b), "l"(c)); return d;
}
__device__ __forceinline__ float lrelu(float x) { return x > 0.f ? x : 0.2f * x; }

// ---------------- kernel 0a: constant head bias ----------------
__global__ void k_setup(const float* __restrict__ Ws1, const float* __restrict__ bs1,
                        const float* __restrict__ vn) {
    int h = threadIdx.x;  // 128 threads
    float s = bs1[h];
    const float* row = Ws1 + (size_t)h * 512 + 256;
#pragma unroll 8
    for (int d = 0; d < 256; ++d) s += row[d] * vn[d];
    g_cvec[h] = s;
}

// ---------------- kernel 0b: transpose Wa, zero u-out and counters ----------------
__global__ void k_prep(const float* __restrict__ Wa, float* __restrict__ out_u) {
    int idx = blockIdx.x * blockDim.x + threadIdx.x;   // grid covers 262144
    if (idx < DMODEL * DU) {
        int u = idx & (DU - 1);
        int d = idx >> 10;
        g_WaT[idx] = Wa[(size_t)u * DMODEL + d];
    }
    if (idx < BATCH * DU) out_u[idx] = 0.f;
    if (idx < BATCH) g_count[idx] = 0;
}

// ---------------- kernel 1: token pass ----------------
// grid: 4096 blocks x 256 thr, 32 tokens/block.
// smem: hT[256][34] + ws[128][257] + hdn[32][132] + ws2s[128] + stv[32] + sq[32] + sr[32]
__global__ __launch_bounds__(256) void k_tokens(
    const int* __restrict__ q_seq, const int* __restrict__ r_seq,
    const float* __restrict__ t_seq, const float* __restrict__ mask,
    const float* __restrict__ q_tab, const float* __restrict__ r_tab,
    const float* __restrict__ Ws1, const float* __restrict__ Ws2,
    const float* __restrict__ bs2, float* __restrict__ outA)
{
    extern __shared__ float sm[];
    float* hT   = sm;                    // 256*34
    float* ws   = hT + 256 * 34;         // 128*257
    float* hdn  = ws + 128 * 257;        // 32*132
    float* ws2s = hdn + 32 * 132;        // 128
    float* stv  = ws2s + 128;            // 32
    int*   sq   = (int*)(stv + 32);      // 32
    int*   sr   = sq + 32;               // 32

    const int tid  = threadIdx.x;
    const int tok0 = blockIdx.x * 32;
    const int b    = tok0 >> 11;

    if (tid < 32) {
        sq[tid]  = q_seq[tok0 + tid];
        sr[tid]  = r_seq[tok0 + tid];
        stv[tid] = t_seq[tok0 + tid];
    }
    if (tid < 128) ws2s[tid] = Ws2[tid];
    // stage Ws1[:, 0:256] into smem (coalesced)
    for (int idx = tid; idx < 128 * 256; idx += 256) {
        int hh = idx >> 8, dd = idx & 255;
        ws[hh * 257 + dd] = Ws1[hh * 512 + dd];
    }
    __syncthreads();

    // Phase A: build h_events, write smem transposed + global scratch
    {
        const int d = tid;
        const float dd = (float)(d & 127);
        const float freq = expf(dd * (-9.2103403719761836f / 128.f));
        const bool is_sin = d < 128;
#pragma unroll 4
        for (int t = 0; t < 32; ++t) {
            float arg = stv[t] * freq;
            float tv  = is_sin ? sinf(arg) : cosf(arg);
            float val = q_tab[(size_t)sq[t] * 256 + d] + r_tab[sr[t] * 256 + d] + tv;
            hT[d * 34 + t] = val;
            g_hev[((size_t)(tok0 + t)) * 256 + d] = val;
        }
    }
    __syncthreads();

    // Phase B: hdn = leaky(h @ Ws1a^T + cvec) — FFMA2 over token pairs
    {
        const int hh   = tid & 127;
        const int half = tid >> 7;          // tokens [half*16, half*16+16)
        ull acc[8];
#pragma unroll
        for (int p = 0; p < 8; ++p) acc[p] = 0ull;
        const float* wr = &ws[hh * 257];
#pragma unroll 4
        for (int d = 0; d < 256; ++d) {
            ull w2 = pk2(wr[d]);
            const ull* hp = (const ull*)&hT[d * 34 + half * 16];
#pragma unroll
            for (int p = 0; p < 8; ++p) acc[p] = fma2(hp[p], w2, acc[p]);
        }
        float c = g_cvec[hh];
#pragma unroll
        for (int p = 0; p < 8; ++p) {
            float2 v = unpk(acc[p]);
            int t = half * 16 + 2 * p;
            hdn[t * 132 + hh]       = lrelu(v.x + c);
            hdn[(t + 1) * 132 + hh] = lrelu(v.y + c);
        }
    }
    __syncthreads();

    // Phase C: logits, sigmoid, compaction. warp w -> tokens [4w, 4w+4)
    {
        const int w = tid >> 5, l = tid & 31;
        const float b2 = bs2[0];
#pragma unroll
        for (int k = 0; k < 4; ++k) {
            int t = w * 4 + k;
            float s = hdn[t * 132 + l]      * ws2s[l]
                    + hdn[t * 132 + l + 32] * ws2s[l + 32]
                    + hdn[t * 132 + l + 64] * ws2s[l + 64]
                    + hdn[t * 132 + l + 96] * ws2s[l + 96];
#pragma unroll
            for (int off = 16; off; off >>= 1) s += __shfl_xor_sync(0xffffffffu, s, off);
            if (l == 0) {
                float logit = s + b2;
                float a = mask[tok0 + t] / (1.f + expf(-logit * 100.f));
                outA[tok0 + t]   = a;
                g_aval[tok0 + t] = a;
                if (a > 1e-10f) {
                    int slot = atomicAdd(&g_count[b], 1);
                    g_active[b * LSEQ + slot] = (tok0 & (LSEQ - 1)) + t;
                }
            }
        }
    }
}

// ---------------- kernel 2: weighted aggregator GEMM over active tokens ----------------
// grid: (8 splits, 64 batches) x 256 thr. Each thread owns 4 u-cols, tiles of 32 tokens.
#define KAGG_S 8
__global__ __launch_bounds__(256, 1) void k_agg(const float* __restrict__ ba,
                                                float* __restrict__ out_u)
{
    __shared__ __align__(16) float hT2[256 * 34];
    __shared__ float sa[32];
    __shared__ int   stok[32];

    const int tid = threadIdx.x;
    const int b   = blockIdx.y;
    const int s   = blockIdx.x;
    const int cnt = g_count[b];
    const int u0  = tid * 4;

    const float4 bav = *(const float4*)&ba[u0];
    float acc0 = 0.f, acc1 = 0.f, acc2 = 0.f, acc3 = 0.f;

    for (int base = s * 32; base < cnt; base += KAGG_S * 32) {
        if (tid < 32) {
            int slot = base + tid;
            int tok = (slot < cnt) ? g_active[b * LSEQ + slot] : -1;
            stok[tid] = tok;
            sa[tid] = (tok >= 0) ? g_aval[b * LSEQ + tok] : 0.f;
        }
        __syncthreads();
        // load h tile transposed: thread = d
#pragma unroll 4
        for (int t = 0; t < 32; ++t) {
            int tok = stok[t];
            float v = (tok >= 0) ? g_hev[(((size_t)b * LSEQ) + tok) * 256 + tid] : 0.f;
            hT2[tid * 34 + t] = v;
        }
        __syncthreads();

        ull C[64];
#pragma unroll
        for (int i = 0; i < 64; ++i) C[i] = 0ull;

#pragma unroll 2
        for (int d = 0; d < 256; ++d) {
            const float4 w4 = *(const float4*)&g_WaT[d * DU + u0];
            ull w0 = pk2(w4.x), w1 = pk2(w4.y), w2 = pk2(w4.z), w3 = pk2(w4.w);
            const ull* hp = (const ull*)&hT2[d * 34];
#pragma unroll
            for (int p = 0; p < 16; ++p) {
                ull h2 = hp[p];
                C[p * 4 + 0] = fma2(h2, w0, C[p * 4 + 0]);
                C[p * 4 + 1] = fma2(h2, w1, C[p * 4 + 1]);
                C[p * 4 + 2] = fma2(h2, w2, C[p * 4 + 2]);
                C[p * 4 + 3] = fma2(h2, w3, C[p * 4 + 3]);
            }
        }

#pragma unroll
        for (int p = 0; p < 16; ++p) {
            float a0 = sa[2 * p], a1 = sa[2 * p + 1];
            float2 c0 = unpk(C[p * 4 + 0]);
            float2 c1 = unpk(C[p * 4 + 1]);
            float2 c2 = unpk(C[p * 4 + 2]);
            float2 c3 = unpk(C[p * 4 + 3]);
            acc0 += a0 * lrelu(c0.x + bav.x) + a1 * lrelu(c0.y + bav.x);
            acc1 += a0 * lrelu(c1.x + bav.y) + a1 * lrelu(c1.y + bav.y);
            acc2 += a0 * lrelu(c2.x + bav.z) + a1 * lrelu(c2.y + bav.z);
            acc3 += a0 * lrelu(c3.x + bav.w) + a1 * lrelu(c3.y + bav.w);
        }
        __syncthreads();
    }

    atomicAdd(&out_u[b * DU + u0 + 0], acc0);
    atomicAdd(&out_u[b * DU + u0 + 1], acc1);
    atomicAdd(&out_u[b * DU + u0 + 2], acc2);
    atomicAdd(&out_u[b * DU + u0 + 3], acc3);
}

// ---------------- launch ----------------
extern "C" void kernel_launch(void* const* d_in, const int* in_sizes, int n_in,
                              void* d_out, int out_size) {
    const int*   q_seq = (const int*)d_in[0];
    const int*   r_seq = (const int*)d_in[1];
    const float* t_seq = (const float*)d_in[2];
    const float* mask  = (const float*)d_in[3];
    const float* q_tab = (const float*)d_in[4];
    const float* r_tab = (const float*)d_in[5];
    const float* vn    = (const float*)d_in[6];
    const float* Ws1   = (const float*)d_in[7];
    const float* bs1   = (const float*)d_in[8];
    const float* Ws2   = (const float*)d_in[9];
    const float* bs2   = (const float*)d_in[10];
    const float* Wa    = (const float*)d_in[11];
    const float* ba    = (const float*)d_in[12];

    float* out_u = (float*)d_out;            // (64, 1024)
    float* outA  = out_u + BATCH * DU;       // (64, 2048)

    k_setup<<<1, 128>>>(Ws1, bs1, vn);
    k_prep<<<(DMODEL * DU + 255) / 256, 256>>>(Wa, out_u);

    size_t smem1 = (size_t)(256 * 34 + 128 * 257 + 32 * 132 + 128 + 32) * sizeof(float)
                 + 64 * sizeof(int);
    cudaFuncSetAttribute(k_tokens, cudaFuncAttributeMaxDynamicSharedMemorySize, (int)smem1);
    k_tokens<<<NTOK / 32, 256, smem1>>>(q_seq, r_seq, t_seq, mask,
                                        q_tab, r_tab, Ws1, Ws2, bs2, outA);

    k_agg<<<dim3(KAGG_S, BATCH), 256>>>(ba, out_u);
}

// round 2
// speedup vs baseline: 1.3484x; 1.3484x over previous
#include <cuda_runtime.h>
#include <cuda_bf16.h>
#include <math.h>

typedef unsigned long long ull;

#define BATCH 64
#define LSEQ  2048
#define DMODEL 256
#define DU 1024
#define HHID 128
#define NTOK (BATCH*LSEQ)
#define TPT 64                      // tokens per tile in k_tokens
#define NTILE (NTOK/TPT)            // 2048
#define KAGG_S 16

// ---------------- scratch (device globals; no allocs allowed) ----------------
__device__ float g_hev[(size_t)NTOK * DMODEL];     // token features
__device__ float g_WaT[(DMODEL + 2) * DU];         // Wa transposed [d][u], +2 pad rows for prefetch
__device__ float g_cvec[HHID];                     // Ws1[:,D:]@vn + bs1
__device__ float g_aval[NTOK];                     // A_hat values
__device__ int   g_active[NTOK];                   // compacted local token ids per batch
__device__ int   g_count[BATCH];
__device__ int   g_tile;                           // dynamic tile counter

// ---------------- f32x2 packed helpers ----------------
__device__ __forceinline__ ull pk2(float v) {
    ull r; asm("mov.b64 %0, {%1, %1};" : "=l"(r) : "f"(v)); return r;
}
__device__ __forceinline__ float2 unpk(ull v) {
    float2 r; asm("mov.b64 {%0, %1}, %2;" : "=f"(r.x), "=f"(r.y) : "l"(v)); return r;
}
__device__ __forceinline__ ull fma2(ull a, ull b, ull c) {
    ull d; asm("fma.rn.f32x2 %0, %1, %2, %3;" : "=l"(d) : "l"(a), "l"(b), "l"(c)); return d;
}
__device__ __forceinline__ float lrelu(float x) { return x > 0.f ? x : 0.2f * x; }

// ---------------- kernel 0a: constant head bias (one warp per h) ----------------
__global__ void k_setup(const float* __restrict__ Ws1, const float* __restrict__ bs1,
                        const float* __restrict__ vn) {
    int h = blockIdx.x * (blockDim.x >> 5) + (threadIdx.x >> 5);
    int l = threadIdx.x & 31;
    if (h >= HHID) return;
    const float* row = Ws1 + (size_t)h * 512 + 256;
    float s = 0.f;
#pragma unroll
    for (int d = l; d < 256; d += 32) s += row[d] * vn[d];
#pragma unroll
    for (int off = 16; off; off >>= 1) s += __shfl_xor_sync(0xffffffffu, s, off);
    if (l == 0) g_cvec[h] = s + bs1[h];
}

// ---------------- kernel 0b: transpose Wa, zero outputs/counters ----------------
__global__ void k_prep(const float* __restrict__ Wa, float* __restrict__ out_u) {
    int idx = blockIdx.x * blockDim.x + threadIdx.x;   // covers 262144
    if (idx < DMODEL * DU) {
        int u = idx & (DU - 1);
        int d = idx >> 10;
        g_WaT[idx] = Wa[(size_t)u * DMODEL + d];
    }
    if (idx < BATCH * DU) out_u[idx] = 0.f;
    if (idx < BATCH) g_count[idx] = 0;
    if (idx == 0) g_tile = 0;
}

// ---------------- kernel 1: persistent token pass ----------------
// grid: 148 blocks x 256 thr. Ws1 staged ONCE per block. Dynamic tile counter.
// smem: ws[128][257] + hT[256][66] + sq[64] + sr[64] + stv[64] + stile
__global__ __launch_bounds__(256) void k_tokens(
    const int* __restrict__ q_seq, const int* __restrict__ r_seq,
    const float* __restrict__ t_seq, const float* __restrict__ mask,
    const float* __restrict__ q_tab, const float* __restrict__ r_tab,
    const float* __restrict__ Ws1, const float* __restrict__ Ws2,
    const float* __restrict__ bs2, float* __restrict__ outA)
{
    extern __shared__ float sm[];
    float* ws  = sm;                       // 128*257 = 32896 floats
    float* hT  = ws + 128 * 257;           // 256*66  = 16896 floats (8B-aligned offset)
    int*   sq  = (int*)(hT + 256 * 66);    // 64
    int*   sr  = sq + 64;                  // 64
    float* stv = (float*)(sr + 64);        // 64
    int*   stile = (int*)(stv + 64);       // 1

    const int tid = threadIdx.x;
    const int w   = tid >> 5;              // warp 0..7
    const int l   = tid & 31;

    // stage Ws1[:, 0:256] into smem once (coalesced)
    for (int idx = tid; idx < 128 * 256; idx += 256) {
        int hh = idx >> 8, dd = idx & 255;
        ws[hh * 257 + dd] = Ws1[hh * 512 + dd];
    }

    // per-lane constants for epilogue: h = l + 32j
    float w2r[4], cr[4];
#pragma unroll
    for (int j = 0; j < 4; ++j) {
        w2r[j] = Ws2[l + 32 * j];
        cr[j]  = g_cvec[l + 32 * j];
    }
    const float b2v = bs2[0];

    // phase A per-thread constants: d = tid
    const int   d_my   = tid;
    const float ddf    = (float)(d_my & 127);
    const float freq   = expf(ddf * (-9.2103403719761836f / 128.f));
    const bool  is_sin = d_my < 128;

    if (tid == 0) *stile = atomicAdd(&g_tile, 1);
    __syncthreads();

    int tile = *stile;
    while (tile < NTILE) {
        const int tok0 = tile * TPT;
        const int b    = tok0 >> 11;

        if (tid < TPT) {
            sq[tid]  = q_seq[tok0 + tid];
            sr[tid]  = r_seq[tok0 + tid];
            stv[tid] = t_seq[tok0 + tid];
        }
        __syncthreads();

        // ---- Phase A: build h_events into hT (transposed) + g_hev ----
        {
            float* gout = g_hev + (size_t)tok0 * 256 + d_my;
#pragma unroll 4
            for (int t = 0; t < TPT; ++t) {
                float arg = stv[t] * freq;
                float tv  = is_sin ? sinf(arg) : cosf(arg);
                float val = q_tab[(size_t)sq[t] * 256 + d_my] + r_tab[sr[t] * 256 + d_my] + tv;
                hT[d_my * 66 + t] = val;
                gout[(size_t)t * 256] = val;
            }
        }
        __syncthreads();

        // ---- Phase B: acc[j][tp] = sum_d w[l+32j][d] * hT[d][8w+2tp..+1] ----
        {
            ull acc[4][4];
#pragma unroll
            for (int j = 0; j < 4; ++j)
#pragma unroll
                for (int p = 0; p < 4; ++p) acc[j][p] = 0ull;

            const float* wp0 = ws + (l +  0) * 257;
            const float* wp1 = ws + (l + 32) * 257;
            const float* wp2 = ws + (l + 64) * 257;
            const float* wp3 = ws + (l + 96) * 257;
            const float* hbase = hT + (w << 3);

#pragma unroll 4
            for (int d = 0; d < 256; ++d) {
                ull wv0 = pk2(wp0[d]);
                ull wv1 = pk2(wp1[d]);
                ull wv2 = pk2(wp2[d]);
                ull wv3 = pk2(wp3[d]);
                const ull* hp = (const ull*)(hbase + d * 66);
                ull h0 = hp[0], h1 = hp[1], h2 = hp[2], h3 = hp[3];
                acc[0][0] = fma2(h0, wv0, acc[0][0]);
                acc[1][0] = fma2(h0, wv1, acc[1][0]);
                acc[2][0] = fma2(h0, wv2, acc[2][0]);
                acc[3][0] = fma2(h0, wv3, acc[3][0]);
                acc[0][1] = fma2(h1, wv0, acc[0][1]);
                acc[1][1] = fma2(h1, wv1, acc[1][1]);
                acc[2][1] = fma2(h1, wv2, acc[2][1]);
                acc[3][1] = fma2(h1, wv3, acc[3][1]);
                acc[0][2] = fma2(h2, wv0, acc[0][2]);
                acc[1][2] = fma2(h2, wv1, acc[1][2]);
                acc[2][2] = fma2(h2, wv2, acc[2][2]);
                acc[3][2] = fma2(h2, wv3, acc[3][2]);
                acc[0][3] = fma2(h3, wv0, acc[0][3]);
                acc[1][3] = fma2(h3, wv1, acc[1][3]);
                acc[2][3] = fma2(h3, wv2, acc[2][3]);
                acc[3][3] = fma2(h3, wv3, acc[3][3]);
            }

            // ---- epilogue: logit per token via warp shuffle reduce ----
#pragma unroll
            for (int p = 0; p < 4; ++p) {
                float sx = 0.f, sy = 0.f;
#pragma unroll
                for (int j = 0; j < 4; ++j) {
                    float2 v = unpk(acc[j][p]);
                    sx += w2r[j] * lrelu(v.x + cr[j]);
                    sy += w2r[j] * lrelu(v.y + cr[j]);
                }
#pragma unroll
                for (int off = 16; off; off >>= 1) {
                    sx += __shfl_xor_sync(0xffffffffu, sx, off);
                    sy += __shfl_xor_sync(0xffffffffu, sy, off);
                }
                if (l == 0) {
                    int t0 = tok0 + (w << 3) + 2 * p;
#pragma unroll
                    for (int k = 0; k < 2; ++k) {
                        int   t     = t0 + k;
                        float logit = (k ? sy : sx) + b2v;
                        float a = mask[t] / (1.f + expf(-logit * 100.f));
                        outA[t]   = a;
                        g_aval[t] = a;
                        if (a > 1e-10f) {
                            int slot = atomicAdd(&g_count[b], 1);
                            g_active[b * LSEQ + slot] = t & (LSEQ - 1);
                        }
                    }
                }
            }
        }

        if (tid == 0) *stile = atomicAdd(&g_tile, 1);
        __syncthreads();
        tile = *stile;
    }
}

// ---------------- kernel 2: weighted aggregator GEMM over active tokens ----------------
// grid: (16 splits, 64 batches) x 256 thr. 4 u-cols/thread, 32-token tiles,
// depth-2 software prefetch on the WaT stream (covers L2 latency).
__global__ __launch_bounds__(256, 1) void k_agg(const float* __restrict__ ba,
                                                float* __restrict__ out_u)
{
    __shared__ __align__(16) float hT2[256 * 34];
    __shared__ float sa[32];
    __shared__ int   stok[32];

    const int tid = threadIdx.x;
    const int b   = blockIdx.y;
    const int s   = blockIdx.x;
    const int cnt = g_count[b];
    const int u0  = tid * 4;

    const float4 bav = *(const float4*)&ba[u0];
    float acc0 = 0.f, acc1 = 0.f, acc2 = 0.f, acc3 = 0.f;

    for (int base = s * 32; base < cnt; base += KAGG_S * 32) {
        if (tid < 32) {
            int slot = base + tid;
            int tok = (slot < cnt) ? g_active[b * LSEQ + slot] : -1;
            stok[tid] = tok;
            sa[tid] = (tok >= 0) ? g_aval[b * LSEQ + tok] : 0.f;
        }
        __syncthreads();
#pragma unroll 4
        for (int t = 0; t < 32; ++t) {
            int tok = stok[t];
            float v = (tok >= 0) ? g_hev[(((size_t)b * LSEQ) + tok) * 256 + tid] : 0.f;
            hT2[tid * 34 + t] = v;
        }
        __syncthreads();

        ull C[64];
#pragma unroll
        for (int i = 0; i < 64; ++i) C[i] = 0ull;

        // depth-2 prefetch pipeline on WaT (padded to 258 rows, so d+2 always valid)
        float4 wreg[2];
        wreg[0] = *(const float4*)&g_WaT[0 * DU + u0];
        wreg[1] = *(const float4*)&g_WaT[1 * DU + u0];

#pragma unroll 1
        for (int d = 0; d < 256; ++d) {
            float4 wc = wreg[d & 1];
            wreg[d & 1] = *(const float4*)&g_WaT[(d + 2) * DU + u0];
            ull w0 = pk2(wc.x), w1 = pk2(wc.y), w2 = pk2(wc.z), w3 = pk2(wc.w);
            const ull* hp = (const ull*)&hT2[d * 34];
#pragma unroll
            for (int p = 0; p < 16; ++p) {
                ull h2 = hp[p];
                C[p * 4 + 0] = fma2(h2, w0, C[p * 4 + 0]);
                C[p * 4 + 1] = fma2(h2, w1, C[p * 4 + 1]);
                C[p * 4 + 2] = fma2(h2, w2, C[p * 4 + 2]);
                C[p * 4 + 3] = fma2(h2, w3, C[p * 4 + 3]);
            }
        }

#pragma unroll
        for (int p = 0; p < 16; ++p) {
            float a0 = sa[2 * p], a1 = sa[2 * p + 1];
            float2 c0 = unpk(C[p * 4 + 0]);
            float2 c1 = unpk(C[p * 4 + 1]);
            float2 c2 = unpk(C[p * 4 + 2]);
            float2 c3 = unpk(C[p * 4 + 3]);
            acc0 += a0 * lrelu(c0.x + bav.x) + a1 * lrelu(c0.y + bav.x);
            acc1 += a0 * lrelu(c1.x + bav.y) + a1 * lrelu(c1.y + bav.y);
            acc2 += a0 * lrelu(c2.x + bav.z) + a1 * lrelu(c2.y + bav.z);
            acc3 += a0 * lrelu(c3.x + bav.w) + a1 * lrelu(c3.y + bav.w);
        }
        __syncthreads();
    }

    atomicAdd(&out_u[b * DU + u0 + 0], acc0);
    atomicAdd(&out_u[b * DU + u0 + 1], acc1);
    atomicAdd(&out_u[b * DU + u0 + 2], acc2);
    atomicAdd(&out_u[b * DU + u0 + 3], acc3);
}

// ---------------- launch ----------------
extern "C" void kernel_launch(void* const* d_in, const int* in_sizes, int n_in,
                              void* d_out, int out_size) {
    const int*   q_seq = (const int*)d_in[0];
    const int*   r_seq = (const int*)d_in[1];
    const float* t_seq = (const float*)d_in[2];
    const float* mask  = (const float*)d_in[3];
    const float* q_tab = (const float*)d_in[4];
    const float* r_tab = (const float*)d_in[5];
    const float* vn    = (const float*)d_in[6];
    const float* Ws1   = (const float*)d_in[7];
    const float* bs1   = (const float*)d_in[8];
    const float* Ws2   = (const float*)d_in[9];
    const float* bs2   = (const float*)d_in[10];
    const float* Wa    = (const float*)d_in[11];
    const float* ba    = (const float*)d_in[12];

    float* out_u = (float*)d_out;            // (64, 1024)
    float* outA  = out_u + BATCH * DU;       // (64, 2048)

    k_setup<<<4, 1024>>>(Ws1, bs1, vn);
    k_prep<<<(DMODEL * DU + 255) / 256, 256>>>(Wa, out_u);

    size_t smem1 = (size_t)(128 * 257 + 256 * 66) * sizeof(float)
                 + 64 * 2 * sizeof(int) + 64 * sizeof(float) + 16;
    cudaFuncSetAttribute(k_tokens, cudaFuncAttributeMaxDynamicSharedMemorySize, (int)smem1);
    k_tokens<<<148, 256, smem1>>>(q_seq, r_seq, t_seq, mask,
                                  q_tab, r_tab, Ws1, Ws2, bs2, outA);

    k_agg<<<dim3(KAGG_S, BATCH), 256>>>(ba, out_u);
}

// round 4
// speedup vs baseline: 2.1096x; 1.5646x over previous
#include <cuda_runtime.h>
#include <cuda_bf16.h>
#include <math.h>
#include <stdint.h>

typedef unsigned long long ull;

#define BATCH 64
#define LSEQ  2048
#define DMODEL 256
#define DU 1024
#define HHID 128
#define NTOK (BATCH*LSEQ)
#define TPT 64
#define NTILE (NTOK/TPT)

// ---------------- device scratch ----------------
__device__ __nv_bfloat16 g_hev_hi[(size_t)NTOK * DMODEL];
__device__ __nv_bfloat16 g_hev_lo[(size_t)NTOK * DMODEL];
__device__ __nv_bfloat16 g_Wa_hi[DU * DMODEL];
__device__ __nv_bfloat16 g_Wa_lo[DU * DMODEL];
__device__ float g_cvec[HHID];
__device__ float g_aval[NTOK];
__device__ int   g_active[NTOK];
__device__ int   g_count[BATCH];
__device__ int   g_tile;

// ---------------- f32x2 helpers ----------------
__device__ __forceinline__ ull pk2(float v) {
    ull r; asm("mov.b64 %0, {%1, %1};" : "=l"(r) : "f"(v)); return r;
}
__device__ __forceinline__ float2 unpk(ull v) {
    float2 r; asm("mov.b64 {%0, %1}, %2;" : "=f"(r.x), "=f"(r.y) : "l"(v)); return r;
}
__device__ __forceinline__ ull fma2(ull a, ull b, ull c) {
    ull d; asm("fma.rn.f32x2 %0, %1, %2, %3;" : "=l"(d) : "l"(a), "l"(b), "l"(c)); return d;
}
__device__ __forceinline__ float lrelu(float x) { return x > 0.f ? x : 0.2f * x; }

// bf16 HMMA: d += a(16x16) * b(16x8), fp32 accumulate (sm_80+ baseline)
__device__ __forceinline__ void mma16816(float* d, const uint32_t* a, const uint32_t* b) {
    asm volatile(
        "mma.sync.aligned.m16n8k16.row.col.f32.bf16.bf16.f32 "
        "{%0,%1,%2,%3}, {%4,%5,%6,%7}, {%8,%9}, {%0,%1,%2,%3};"
        : "+f"(d[0]), "+f"(d[1]), "+f"(d[2]), "+f"(d[3])
        : "r"(a[0]), "r"(a[1]), "r"(a[2]), "r"(a[3]), "r"(b[0]), "r"(b[1]));
}

// ---------------- kernel 0a ----------------
__global__ void k_setup(const float* __restrict__ Ws1, const float* __restrict__ bs1,
                        const float* __restrict__ vn) {
    int h = blockIdx.x * (blockDim.x >> 5) + (threadIdx.x >> 5);
    int l = threadIdx.x & 31;
    if (h >= HHID) return;
    const float* row = Ws1 + (size_t)h * 512 + 256;
    float s = 0.f;
#pragma unroll
    for (int d = l; d < 256; d += 32) s += row[d] * vn[d];
#pragma unroll
    for (int off = 16; off; off >>= 1) s += __shfl_xor_sync(0xffffffffu, s, off);
    if (l == 0) g_cvec[h] = s + bs1[h];
}

// ---------------- kernel 0b: Wa -> bf16 hi/lo, zero outputs ----------------
__global__ void k_prep(const float* __restrict__ Wa, float* __restrict__ out_u) {
    int idx = blockIdx.x * blockDim.x + threadIdx.x;   // covers 262144
    if (idx < DU * DMODEL) {
        float v = Wa[idx];
        __nv_bfloat16 hi = __float2bfloat16(v);
        __nv_bfloat16 lo = __float2bfloat16(v - __bfloat162float(hi));
        g_Wa_hi[idx] = hi;
        g_Wa_lo[idx] = lo;
    }
    if (idx < BATCH * DU) out_u[idx] = 0.f;
    if (idx < BATCH) g_count[idx] = 0;
    if (idx == 0) g_tile = 0;
}

// ---------------- kernel 1: persistent token pass (512 threads, fp32 logits) ----------------
__global__ __launch_bounds__(512) void k_tokens(
    const int* __restrict__ q_seq, const int* __restrict__ r_seq,
    const float* __restrict__ t_seq, const float* __restrict__ mask,
    const float* __restrict__ q_tab, const float* __restrict__ r_tab,
    const float* __restrict__ Ws1, const float* __restrict__ Ws2,
    const float* __restrict__ bs2, float* __restrict__ outA)
{
    extern __shared__ float sm[];
    float* ws  = sm;                       // 128*257
    float* hT  = ws + 128 * 257;           // 256*66
    int*   sq  = (int*)(hT + 256 * 66);    // 64
    int*   sr  = sq + 64;                  // 64
    float* stv = (float*)(sr + 64);        // 64
    int*   stile = (int*)(stv + 64);

    const int tid = threadIdx.x;
    const int w   = tid >> 5;              // 0..15
    const int l   = tid & 31;

    for (int idx = tid; idx < 128 * 256; idx += 512) {
        int hh = idx >> 8, dd = idx & 255;
        ws[hh * 257 + dd] = Ws1[hh * 512 + dd];
    }

    float w2r[4], cr[4];
#pragma unroll
    for (int j = 0; j < 4; ++j) {
        w2r[j] = Ws2[l + 32 * j];
        cr[j]  = g_cvec[l + 32 * j];
    }
    const float b2v = bs2[0];

    const int   d_my   = tid & 255;
    const int   tseg   = tid >> 8;         // 0/1 -> token halves
    const float ddf    = (float)(d_my & 127);
    const float freq   = expf(ddf * (-9.2103403719761836f / 128.f));
    const bool  is_sin = d_my < 128;

    if (tid == 0) *stile = atomicAdd(&g_tile, 1);
    __syncthreads();

    int tile = *stile;
    while (tile < NTILE) {
        const int tok0 = tile * TPT;
        const int b    = tok0 >> 11;

        if (tid < TPT) {
            sq[tid]  = q_seq[tok0 + tid];
            sr[tid]  = r_seq[tok0 + tid];
            stv[tid] = t_seq[tok0 + tid];
        }
        __syncthreads();

        // ---- Phase A: gather + trig, write f32 smem + bf16 hi/lo global ----
        {
            const int t0 = tseg * 32;
            __nv_bfloat16* ghi = g_hev_hi + ((size_t)(tok0 + t0)) * 256 + d_my;
            __nv_bfloat16* glo = g_hev_lo + ((size_t)(tok0 + t0)) * 256 + d_my;
#pragma unroll 4
            for (int t = 0; t < 32; ++t) {
                float arg = stv[t0 + t] * freq;
                float tv  = is_sin ? sinf(arg) : cosf(arg);
                float val = q_tab[(size_t)sq[t0 + t] * 256 + d_my]
                          + r_tab[sr[t0 + t] * 256 + d_my] + tv;
                hT[d_my * 66 + t0 + t] = val;
                __nv_bfloat16 hb = __float2bfloat16(val);
                ghi[(size_t)t * 256] = hb;
                glo[(size_t)t * 256] = __float2bfloat16(val - __bfloat162float(hb));
            }
        }
        __syncthreads();

        // ---- Phase B: fp32 FFMA2 logits; warp w -> tokens [4w,4w+4) ----
        {
            ull acc[4][2];
#pragma unroll
            for (int j = 0; j < 4; ++j) { acc[j][0] = 0ull; acc[j][1] = 0ull; }
            const float* wp0 = ws + (l +  0) * 257;
            const float* wp1 = ws + (l + 32) * 257;
            const float* wp2 = ws + (l + 64) * 257;
            const float* wp3 = ws + (l + 96) * 257;
            const float* hbase = hT + (w << 2);

#pragma unroll 4
            for (int d = 0; d < 256; ++d) {
                ull wv0 = pk2(wp0[d]);
                ull wv1 = pk2(wp1[d]);
                ull wv2 = pk2(wp2[d]);
                ull wv3 = pk2(wp3[d]);
                const ull* hp = (const ull*)(hbase + d * 66);
                ull h0 = hp[0], h1 = hp[1];
                acc[0][0] = fma2(h0, wv0, acc[0][0]);
                acc[1][0] = fma2(h0, wv1, acc[1][0]);
                acc[2][0] = fma2(h0, wv2, acc[2][0]);
                acc[3][0] = fma2(h0, wv3, acc[3][0]);
                acc[0][1] = fma2(h1, wv0, acc[0][1]);
                acc[1][1] = fma2(h1, wv1, acc[1][1]);
                acc[2][1] = fma2(h1, wv2, acc[2][1]);
                acc[3][1] = fma2(h1, wv3, acc[3][1]);
            }

#pragma unroll
            for (int p = 0; p < 2; ++p) {
                float sx = 0.f, sy = 0.f;
#pragma unroll
                for (int j = 0; j < 4; ++j) {
                    float2 v = unpk(acc[j][p]);
                    sx += w2r[j] * lrelu(v.x + cr[j]);
                    sy += w2r[j] * lrelu(v.y + cr[j]);
                }
#pragma unroll
                for (int off = 16; off; off >>= 1) {
                    sx += __shfl_xor_sync(0xffffffffu, sx, off);
                    sy += __shfl_xor_sync(0xffffffffu, sy, off);
                }
                if (l == 0) {
                    int t0 = tok0 + (w << 2) + 2 * p;
#pragma unroll
                    for (int k = 0; k < 2; ++k) {
                        int   t     = t0 + k;
                        float logit = (k ? sy : sx) + b2v;
                        float a = mask[t] / (1.f + expf(-logit * 100.f));
                        outA[t]   = a;
                        g_aval[t] = a;
                        if (a > 1e-10f) {
                            int slot = atomicAdd(&g_count[b], 1);
                            g_active[b * LSEQ + slot] = t & (LSEQ - 1);
                        }
                    }
                }
            }
        }

        if (tid == 0) *stile = atomicAdd(&g_tile, 1);
        __syncthreads();
        tile = *stile;
    }
}

// ---------------- kernel 2: HMMA bf16 hi/lo aggregator ----------------
// grid (8 u-chunks, 64 batches) x 256 thr. tile = 64 tokens x 128 u.
// smem: B[2][128][264h] @0 (135168B), A[2][64][264h] @135168 (67584B), sa/stok.
#define B_OFF    0
#define B_TERM_W 16896         // words per B term (67584B)
#define A_OFF    135168
#define A_TERM_W 8448          // words per A term (33792B)
#define SA_OFF   202752
#define STOK_OFF 203008
#define SMEM_AGG 203264

__global__ __launch_bounds__(256, 1) void k_agg_mma(const float* __restrict__ ba,
                                                    float* __restrict__ out_u)
{
    extern __shared__ char smem[];
    const int tid  = threadIdx.x;
    const int wid  = tid >> 5;
    const int lane = tid & 31;
    const int gid  = lane >> 2;
    const int tig  = lane & 3;
    const int b    = blockIdx.y;
    const int colbase = blockIdx.x * 128;
    const int warpM = wid >> 2;      // 0/1
    const int warpN = wid & 3;       // 0..3

    uint32_t* sB = (uint32_t*)(smem + B_OFF);
    uint32_t* sA = (uint32_t*)(smem + A_OFF);
    float*    sa = (float*)(smem + SA_OFF);
    int*    stok = (int*)(smem + STOK_OFF);

    // stage B (Wa slice hi+lo), pitch 264 halves = 132 words
    for (int i = tid; i < 8192; i += 256) {
        int term = i >> 12;
        int r = (i >> 5) & 127;
        int c = i & 31;
        const __nv_bfloat16* src = term ? g_Wa_lo : g_Wa_hi;
        uint4 v = ((const uint4*)(src + ((size_t)(colbase + r) << 8)))[c];
        *(uint4*)(smem + B_OFF + term * 67584 + r * 528 + c * 16) = v;
    }

    const int cnt = g_count[b];
    float colacc[4][2];
#pragma unroll
    for (int n = 0; n < 4; ++n) { colacc[n][0] = 0.f; colacc[n][1] = 0.f; }
    float ban0[4], ban1[4];
#pragma unroll
    for (int n = 0; n < 4; ++n) {
        int c0 = colbase + warpN * 32 + n * 8 + 2 * tig;
        ban0[n] = ba[c0];
        ban1[n] = ba[c0 + 1];
    }
    __syncthreads();

    for (int t0 = 0; t0 < cnt; t0 += 64) {
        if (tid < 64) {
            int slot = t0 + tid;
            int tok = (slot < cnt) ? g_active[(b << 11) + slot] : 0;
            stok[tid] = tok;
            sa[tid]   = (slot < cnt) ? g_aval[(b << 11) + tok] : 0.f;
        }
        __syncthreads();
        // stage A tile (64 gathered token rows, hi+lo)
        for (int i = tid; i < 4096; i += 256) {
            int term = i >> 11;
            int r = (i >> 5) & 63;
            int c = i & 31;
            const __nv_bfloat16* src = term ? g_hev_lo : g_hev_hi;
            uint4 v = ((const uint4*)(src + (((size_t)(b << 11) + stok[r]) << 8)))[c];
            *(uint4*)(smem + A_OFF + term * 33792 + r * 528 + c * 16) = v;
        }
        __syncthreads();

        float C[2][4][4];
#pragma unroll
        for (int m = 0; m < 2; ++m)
#pragma unroll
            for (int n = 0; n < 4; ++n)
#pragma unroll
                for (int k = 0; k < 4; ++k) C[m][n][k] = 0.f;

#pragma unroll 4
        for (int ks = 0; ks < 16; ++ks) {
            const int kw = ks * 8 + tig;
            uint32_t ah[2][4], al[2][4];
#pragma unroll
            for (int m = 0; m < 2; ++m) {
                int rb = (warpM * 32 + m * 16 + gid) * 132 + kw;
                ah[m][0] = sA[rb];
                ah[m][1] = sA[rb + 8 * 132];
                ah[m][2] = sA[rb + 4];
                ah[m][3] = sA[rb + 8 * 132 + 4];
                al[m][0] = sA[rb + A_TERM_W];
                al[m][1] = sA[rb + A_TERM_W + 8 * 132];
                al[m][2] = sA[rb + A_TERM_W + 4];
                al[m][3] = sA[rb + A_TERM_W + 8 * 132 + 4];
            }
            uint32_t bh[4][2], bl[4][2];
#pragma unroll
            for (int n = 0; n < 4; ++n) {
                int nb = (warpN * 32 + n * 8 + gid) * 132 + kw;
                bh[n][0] = sB[nb];
                bh[n][1] = sB[nb + 4];
                bl[n][0] = sB[nb + B_TERM_W];
                bl[n][1] = sB[nb + B_TERM_W + 4];
            }
#pragma unroll
            for (int m = 0; m < 2; ++m)
#pragma unroll
                for (int n = 0; n < 4; ++n) {
                    mma16816(C[m][n], ah[m], bh[n]);
                    mma16816(C[m][n], ah[m], bl[n]);
                    mma16816(C[m][n], al[m], bh[n]);
                }
        }

        // epilogue: a-weighted lrelu, accumulate per-thread column partials
#pragma unroll
        for (int m = 0; m < 2; ++m) {
            float a0 = sa[warpM * 32 + m * 16 + gid];
            float a1 = sa[warpM * 32 + m * 16 + gid + 8];
#pragma unroll
            for (int n = 0; n < 4; ++n) {
                colacc[n][0] += a0 * lrelu(C[m][n][0] + ban0[n])
                              + a1 * lrelu(C[m][n][2] + ban0[n]);
                colacc[n][1] += a0 * lrelu(C[m][n][1] + ban1[n])
                              + a1 * lrelu(C[m][n][3] + ban1[n]);
            }
        }
        __syncthreads();
    }

    // reduce over gid lanes and write
#pragma unroll
    for (int n = 0; n < 4; ++n)
#pragma unroll
        for (int j = 0; j < 2; ++j) {
            float v = colacc[n][j];
            v += __shfl_xor_sync(0xffffffffu, v, 4);
            v += __shfl_xor_sync(0xffffffffu, v, 8);
            v += __shfl_xor_sync(0xffffffffu, v, 16);
            colacc[n][j] = v;
        }
    if (lane < 4) {
#pragma unroll
        for (int n = 0; n < 4; ++n) {
            int c0 = colbase + warpN * 32 + n * 8 + 2 * lane;
            atomicAdd(&out_u[b * DU + c0],     colacc[n][0]);
            atomicAdd(&out_u[b * DU + c0 + 1], colacc[n][1]);
        }
    }
}

// ---------------- launch ----------------
extern "C" void kernel_launch(void* const* d_in, const int* in_sizes, int n_in,
                              void* d_out, int out_size) {
    const int*   q_seq = (const int*)d_in[0];
    const int*   r_seq = (const int*)d_in[1];
    const float* t_seq = (const float*)d_in[2];
    const float* mask  = (const float*)d_in[3];
    const float* q_tab = (const float*)d_in[4];
    const float* r_tab = (const float*)d_in[5];
    const float* vn    = (const float*)d_in[6];
    const float* Ws1   = (const float*)d_in[7];
    const float* bs1   = (const float*)d_in[8];
    const float* Ws2   = (const float*)d_in[9];
    const float* bs2   = (const float*)d_in[10];
    const float* Wa    = (const float*)d_in[11];
    const float* ba    = (const float*)d_in[12];

    float* out_u = (float*)d_out;            // (64, 1024)
    float* outA  = out_u + BATCH * DU;       // (64, 2048)

    k_setup<<<4, 1024>>>(Ws1, bs1, vn);
    k_prep<<<(DU * DMODEL + 255) / 256, 256>>>(Wa, out_u);

    size_t smem1 = (size_t)(128 * 257 + 256 * 66) * sizeof(float)
                 + 64 * 2 * sizeof(int) + 64 * sizeof(float) + 16;
    cudaFuncSetAttribute(k_tokens, cudaFuncAttributeMaxDynamicSharedMemorySize, (int)smem1);
    k_tokens<<<148, 512, smem1>>>(q_seq, r_seq, t_seq, mask,
                                  q_tab, r_tab, Ws1, Ws2, bs2, outA);

    cudaFuncSetAttribute(k_agg_mma, cudaFuncAttributeMaxDynamicSharedMemorySize, SMEM_AGG);
    k_agg_mma<<<dim3(8, BATCH), 256, SMEM_AGG>>>(ba, out_u);
}

// round 5
// speedup vs baseline: 3.0775x; 1.4588x over previous
#include <cuda_runtime.h>
#include <cuda_bf16.h>
#include <math.h>
#include <stdint.h>

typedef unsigned long long ull;

#define BATCH 64
#define LSEQ  2048
#define DMODEL 256
#define DU 1024
#define HHID 128
#define NTOK (BATCH*LSEQ)
#define TPT 64
#define NTILE (NTOK/TPT)

// ---------------- device scratch ----------------
__device__ __nv_bfloat16 g_hev_hi[(size_t)NTOK * DMODEL];
__device__ __nv_bfloat16 g_hev_lo[(size_t)NTOK * DMODEL];
__device__ __nv_bfloat16 g_Wa_hi[DU * DMODEL];
__device__ __nv_bfloat16 g_Wa_lo[DU * DMODEL];
__device__ float g_cvec[HHID];
__device__ float g_aval[NTOK];
__device__ int   g_active[NTOK];
__device__ int   g_count[BATCH];
__device__ int   g_tile;

// ---------------- helpers ----------------
__device__ __forceinline__ ull pk2(float v) {
    ull r; asm("mov.b64 %0, {%1, %1};" : "=l"(r) : "f"(v)); return r;
}
__device__ __forceinline__ float2 unpk(ull v) {
    float2 r; asm("mov.b64 {%0, %1}, %2;" : "=f"(r.x), "=f"(r.y) : "l"(v)); return r;
}
__device__ __forceinline__ ull fma2(ull a, ull b, ull c) {
    ull d; asm("fma.rn.f32x2 %0, %1, %2, %3;" : "=l"(d) : "l"(a), "l"(b), "l"(c)); return d;
}
__device__ __forceinline__ float lrelu(float x) { return x > 0.f ? x : 0.2f * x; }

__device__ __forceinline__ uint32_t smem_u32(const void* p) {
    uint32_t a;
    asm("{ .reg .u64 t; cvta.to.shared.u64 t, %1; cvt.u32.u64 %0, t; }" : "=r"(a) : "l"(p));
    return a;
}
__device__ __forceinline__ void mma16816(float* d, const uint32_t* a, const uint32_t* b) {
    asm volatile(
        "mma.sync.aligned.m16n8k16.row.col.f32.bf16.bf16.f32 "
        "{%0,%1,%2,%3}, {%4,%5,%6,%7}, {%8,%9}, {%0,%1,%2,%3};"
        : "+f"(d[0]), "+f"(d[1]), "+f"(d[2]), "+f"(d[3])
        : "r"(a[0]), "r"(a[1]), "r"(a[2]), "r"(a[3]), "r"(b[0]), "r"(b[1]));
}
__device__ __forceinline__ void ldsm4(uint32_t* r, uint32_t addr) {
    asm volatile("ldmatrix.sync.aligned.m8n8.x4.shared.b16 {%0,%1,%2,%3}, [%4];"
        : "=r"(r[0]), "=r"(r[1]), "=r"(r[2]), "=r"(r[3]) : "r"(addr));
}
__device__ __forceinline__ void cp16(uint32_t dst, const void* src) {
    asm volatile("cp.async.cg.shared.global [%0], [%1], 16;" :: "r"(dst), "l"(src));
}
#define CP_COMMIT() asm volatile("cp.async.commit_group;" ::: "memory")
#define CP_WAIT0()  asm volatile("cp.async.wait_group 0;" ::: "memory")

// ---------------- kernel 0a: constant head bias ----------------
__global__ void k_setup(const float* __restrict__ Ws1, const float* __restrict__ bs1,
                        const float* __restrict__ vn) {
    int h = blockIdx.x * (blockDim.x >> 5) + (threadIdx.x >> 5);
    int l = threadIdx.x & 31;
    if (h >= HHID) return;
    const float* row = Ws1 + (size_t)h * 512 + 256;
    float s = 0.f;
#pragma unroll
    for (int d = l; d < 256; d += 32) s += row[d] * vn[d];
#pragma unroll
    for (int off = 16; off; off >>= 1) s += __shfl_xor_sync(0xffffffffu, s, off);
    if (l == 0) g_cvec[h] = s + bs1[h];
}

// ---------------- kernel 0b: Wa -> bf16 hi/lo, zero outputs ----------------
__global__ void k_prep(const float* __restrict__ Wa, float* __restrict__ out_u) {
    int idx = blockIdx.x * blockDim.x + threadIdx.x;
    if (idx < DU * DMODEL) {
        float v = Wa[idx];
        __nv_bfloat16 hi = __float2bfloat16(v);
        __nv_bfloat16 lo = __float2bfloat16(v - __bfloat162float(hi));
        g_Wa_hi[idx] = hi;
        g_Wa_lo[idx] = lo;
    }
    if (idx < BATCH * DU) out_u[idx] = 0.f;
    if (idx < BATCH) g_count[idx] = 0;
    if (idx == 0) g_tile = 0;
}

// ---------------- kernel 1a: embedding + trig -> bf16 hi/lo (streaming) ----------------
__global__ __launch_bounds__(256) void k_emb(
    const int* __restrict__ q_seq, const int* __restrict__ r_seq,
    const float* __restrict__ t_seq,
    const float* __restrict__ q_tab, const float* __restrict__ r_tab)
{
    __shared__ int sq[16], sr[16];
    __shared__ float st[16];
    const int tid = threadIdx.x;
    const int tok0 = blockIdx.x * 16;
    if (tid < 16) {
        sq[tid] = q_seq[tok0 + tid];
        sr[tid] = r_seq[tok0 + tid];
        st[tid] = t_seq[tok0 + tid];
    }
    __syncthreads();
    const int d = tid;
    const float ddf  = (float)(d & 127);
    const float freq = expf(ddf * (-9.2103403719761836f / 128.f));
    const bool is_sin = d < 128;
    __nv_bfloat16* ghi = g_hev_hi + (size_t)tok0 * 256 + d;
    __nv_bfloat16* glo = g_hev_lo + (size_t)tok0 * 256 + d;
#pragma unroll 4
    for (int t = 0; t < 16; ++t) {
        float arg = st[t] * freq;
        float tv  = is_sin ? sinf(arg) : cosf(arg);
        float val = q_tab[(size_t)sq[t] * 256 + d] + r_tab[sr[t] * 256 + d] + tv;
        __nv_bfloat16 hb = __float2bfloat16(val);
        ghi[(size_t)t * 256] = hb;
        glo[(size_t)t * 256] = __float2bfloat16(val - __bfloat162float(hb));
    }
}

// ---------------- kernel 1b: persistent fp32 logits + compaction ----------------
__global__ __launch_bounds__(512) void k_logits(
    const float* __restrict__ mask, const float* __restrict__ Ws1,
    const float* __restrict__ Ws2, const float* __restrict__ bs2,
    float* __restrict__ outA)
{
    extern __shared__ float sm[];
    float* ws  = sm;                      // 128*257
    float* hT  = ws + 128 * 257;          // 256*66
    int*   stile = (int*)(hT + 256 * 66);

    const int tid = threadIdx.x;
    const int w   = tid >> 5;             // 0..15
    const int l   = tid & 31;

    for (int idx = tid; idx < 128 * 256; idx += 512) {
        int hh = idx >> 8, dd = idx & 255;
        ws[hh * 257 + dd] = Ws1[hh * 512 + dd];
    }

    float w2r[4], cr[4];
#pragma unroll
    for (int j = 0; j < 4; ++j) {
        w2r[j] = Ws2[l + 32 * j];
        cr[j]  = g_cvec[l + 32 * j];
    }
    const float b2v = bs2[0];

    // staging ids: tt = token-in-tile, dg -> 32-d chunk
    const int tt = tid & 63;
    const int d0 = (tid >> 6) * 32;

    if (tid == 0) *stile = atomicAdd(&g_tile, 1);
    __syncthreads();

    int tile = *stile;
    while (tile < NTILE) {
        const int tok0 = tile * TPT;
        const int b    = tok0 >> 11;

        // ---- stage hT (f32, transposed) from g_hev hi+lo ----
        {
            const __nv_bfloat16* ph = g_hev_hi + (size_t)(tok0 + tt) * 256 + d0;
            const __nv_bfloat16* pl = g_hev_lo + (size_t)(tok0 + tt) * 256 + d0;
#pragma unroll
            for (int c = 0; c < 4; ++c) {
                uint4 vh = *(const uint4*)(ph + c * 8);
                uint4 vl = *(const uint4*)(pl + c * 8);
                const __nv_bfloat16* hh_ = (const __nv_bfloat16*)&vh;
                const __nv_bfloat16* ll_ = (const __nv_bfloat16*)&vl;
#pragma unroll
                for (int j = 0; j < 8; ++j)
                    hT[(d0 + c * 8 + j) * 66 + tt] =
                        __bfloat162float(hh_[j]) + __bfloat162float(ll_[j]);
            }
        }
        __syncthreads();
        if (tid == 0) *stile = atomicAdd(&g_tile, 1);

        // ---- fp32x2 logits: warp w -> tokens [4w,4w+4) ----
        {
            ull acc[4][2];
#pragma unroll
            for (int j = 0; j < 4; ++j) { acc[j][0] = 0ull; acc[j][1] = 0ull; }
            const float* wp0 = ws + (l +  0) * 257;
            const float* wp1 = ws + (l + 32) * 257;
            const float* wp2 = ws + (l + 64) * 257;
            const float* wp3 = ws + (l + 96) * 257;
            const float* hbase = hT + (w << 2);

#pragma unroll 4
            for (int d = 0; d < 256; ++d) {
                ull wv0 = pk2(wp0[d]);
                ull wv1 = pk2(wp1[d]);
                ull wv2 = pk2(wp2[d]);
                ull wv3 = pk2(wp3[d]);
                const ull* hp = (const ull*)(hbase + d * 66);
                ull h0 = hp[0], h1 = hp[1];
                acc[0][0] = fma2(h0, wv0, acc[0][0]);
                acc[1][0] = fma2(h0, wv1, acc[1][0]);
                acc[2][0] = fma2(h0, wv2, acc[2][0]);
                acc[3][0] = fma2(h0, wv3, acc[3][0]);
                acc[0][1] = fma2(h1, wv0, acc[0][1]);
                acc[1][1] = fma2(h1, wv1, acc[1][1]);
                acc[2][1] = fma2(h1, wv2, acc[2][1]);
                acc[3][1] = fma2(h1, wv3, acc[3][1]);
            }

#pragma unroll
            for (int p = 0; p < 2; ++p) {
                float sx = 0.f, sy = 0.f;
#pragma unroll
                for (int j = 0; j < 4; ++j) {
                    float2 v = unpk(acc[j][p]);
                    sx += w2r[j] * lrelu(v.x + cr[j]);
                    sy += w2r[j] * lrelu(v.y + cr[j]);
                }
#pragma unroll
                for (int off = 16; off; off >>= 1) {
                    sx += __shfl_xor_sync(0xffffffffu, sx, off);
                    sy += __shfl_xor_sync(0xffffffffu, sy, off);
                }
                if (l == 0) {
                    int t0 = tok0 + (w << 2) + 2 * p;
#pragma unroll
                    for (int k = 0; k < 2; ++k) {
                        int   t     = t0 + k;
                        float logit = (k ? sy : sx) + b2v;
                        float a = mask[t] / (1.f + expf(-logit * 100.f));
                        outA[t]   = a;
                        g_aval[t] = a;
                        if (a > 1e-10f) {
                            int slot = atomicAdd(&g_count[b], 1);
                            g_active[b * LSEQ + slot] = t & (LSEQ - 1);
                        }
                    }
                }
            }
        }
        __syncthreads();
        tile = *stile;
    }
}

// ---------------- kernel 2: pipelined HMMA aggregator ----------------
// grid (8 u-chunks, 64 batches) x 256 thr, warp grid 2M x 4N (32tok x 32col).
// smem: B[2 terms][128 rows][132w]  @0       = 135168 B
//       A[2 bufs][2 terms][64][68w] @135168  = 69632 B
//       sa[2][64], stok[2][64]      @204800
#define KA_B_OFF   0
#define KA_A_OFF   135168
#define KA_ABUF    34816
#define KA_ATERM   17408
#define KA_SA_OFF  204800
#define KA_STOK_OFF 205312
#define SMEM_AGG   205824

__global__ __launch_bounds__(256, 1) void k_agg_p(const float* __restrict__ ba,
                                                  float* __restrict__ out_u)
{
    extern __shared__ char smem[];
    const uint32_t sb = smem_u32(smem);
    const int tid  = threadIdx.x;
    const int wid  = tid >> 5;
    const int lane = tid & 31;
    const int gid  = lane >> 2;
    const int b    = blockIdx.y;
    const int colbase = blockIdx.x * 128;
    const int warpM = wid >> 2;      // 0/1
    const int warpN = wid & 3;       // 0..3

    float* sa   = (float*)(smem + KA_SA_OFF);
    int*   stok = (int*)(smem + KA_STOK_OFF);

    // stage B (Wa slice hi+lo), pitch 132 words
    for (int i = tid; i < 8192; i += 256) {
        int term = i >> 12;
        int r = (i >> 5) & 127;
        int c = i & 31;
        const __nv_bfloat16* src = term ? g_Wa_lo : g_Wa_hi;
        uint4 v = ((const uint4*)(src + ((size_t)(colbase + r) << 8)))[c];
        *(uint4*)(smem + KA_B_OFF + term * 67584 + r * 528 + c * 16) = v;
    }

    const int cnt = g_count[b];
    const int ntile = (cnt + 63) >> 6;

    float colacc[4][2];
#pragma unroll
    for (int n = 0; n < 4; ++n) { colacc[n][0] = 0.f; colacc[n][1] = 0.f; }
    float ban0[4], ban1[4];
#pragma unroll
    for (int n = 0; n < 4; ++n) {
        int c0 = colbase + warpN * 32 + n * 8 + 2 * (lane & 3);
        ban0[n] = ba[c0];
        ban1[n] = ba[c0 + 1];
    }

    // prologue: tile 0 metadata + first A chunk
    if (tid < 64 && ntile > 0) {
        int tok = (tid < cnt) ? g_active[(b << 11) + tid] : 0;
        stok[tid] = tok;
        sa[tid]   = (tid < cnt) ? g_aval[(b << 11) + tok] : 0.f;
    }
    __syncthreads();

    // LDSM base addresses (per-thread constants)
    const uint32_t a_ld_base = sb + KA_A_OFF
        + (uint32_t)((lane & 15) * 272 + (lane >> 4) * 16);
    const uint32_t b_ld_base = sb + KA_B_OFF
        + (uint32_t)((warpN * 32 + (lane & 15)) * 528 + (lane >> 4) * 16);

    // issue A(0, kh0)
    if (ntile > 0) {
#pragma unroll
        for (int i = 0; i < 8; ++i) {
            int idx = tid + i * 256;
            int term = idx >> 10;
            int row  = (idx >> 4) & 63;
            int c    = idx & 15;
            const __nv_bfloat16* src = term ? g_hev_lo : g_hev_hi;
            cp16(sb + KA_A_OFF + (uint32_t)(term * KA_ATERM + row * 272 + c * 16),
                 src + (((size_t)(b << 11) + stok[row]) << 8) + (c << 3));
        }
        CP_COMMIT();
    }

    int cur = 0;
    for (int t = 0; t < ntile; ++t, cur ^= 1) {
        const int nxt = cur ^ 1;
        // load next tile metadata (visible after second sync)
        if (tid < 64 && t + 1 < ntile) {
            int slot = ((t + 1) << 6) + tid;
            int tok = (slot < cnt) ? g_active[(b << 11) + slot] : 0;
            stok[nxt * 64 + tid] = tok;
            sa[nxt * 64 + tid]   = (slot < cnt) ? g_aval[(b << 11) + tok] : 0.f;
        }
        CP_WAIT0();
        __syncthreads();                      // A(t,kh0) ready in buf0

        // issue A(t, kh1) -> buf1
#pragma unroll
        for (int i = 0; i < 8; ++i) {
            int idx = tid + i * 256;
            int term = idx >> 10;
            int row  = (idx >> 4) & 63;
            int c    = idx & 15;
            const __nv_bfloat16* src = term ? g_hev_lo : g_hev_hi;
            cp16(sb + KA_A_OFF + KA_ABUF
                     + (uint32_t)(term * KA_ATERM + row * 272 + c * 16),
                 src + (((size_t)(b << 11) + stok[cur * 64 + row]) << 8) + 128 + (c << 3));
        }
        CP_COMMIT();

        float C[2][4][4];
#pragma unroll
        for (int m = 0; m < 2; ++m)
#pragma unroll
            for (int n = 0; n < 4; ++n)
#pragma unroll
                for (int k = 0; k < 4; ++k) C[m][n][k] = 0.f;

        // ---- compute kh = 0 from buf0 ----
#pragma unroll
        for (int ks = 0; ks < 8; ++ks) {
            uint32_t ah[2][4], al[2][4], bh[4][2], bl[4][2], tmp[4];
#pragma unroll
            for (int m = 0; m < 2; ++m) {
                uint32_t ro = (uint32_t)((warpM * 32 + m * 16) * 272 + ks * 32);
                ldsm4(ah[m], a_ld_base + ro);
                ldsm4(al[m], a_ld_base + KA_ATERM + ro);
            }
#pragma unroll
            for (int nc = 0; nc < 2; ++nc) {
                uint32_t no = (uint32_t)(nc * 16 * 528 + ks * 32);
                ldsm4(tmp, b_ld_base + no);
                bh[2 * nc][0] = tmp[0]; bh[2 * nc + 1][0] = tmp[1];
                bh[2 * nc][1] = tmp[2]; bh[2 * nc + 1][1] = tmp[3];
                ldsm4(tmp, b_ld_base + 67584 + no);
                bl[2 * nc][0] = tmp[0]; bl[2 * nc + 1][0] = tmp[1];
                bl[2 * nc][1] = tmp[2]; bl[2 * nc + 1][1] = tmp[3];
            }
#pragma unroll
            for (int m = 0; m < 2; ++m)
#pragma unroll
                for (int n = 0; n < 4; ++n) mma16816(C[m][n], ah[m], bh[n]);
#pragma unroll
            for (int m = 0; m < 2; ++m)
#pragma unroll
                for (int n = 0; n < 4; ++n) mma16816(C[m][n], ah[m], bl[n]);
#pragma unroll
            for (int m = 0; m < 2; ++m)
#pragma unroll
                for (int n = 0; n < 4; ++n) mma16816(C[m][n], al[m], bh[n]);
        }

        CP_WAIT0();
        __syncthreads();                      // A(t,kh1) ready; next stok visible

        // issue A(t+1, kh0) -> buf0
        if (t + 1 < ntile) {
#pragma unroll
            for (int i = 0; i < 8; ++i) {
                int idx = tid + i * 256;
                int term = idx >> 10;
                int row  = (idx >> 4) & 63;
                int c    = idx & 15;
                const __nv_bfloat16* src = term ? g_hev_lo : g_hev_hi;
                cp16(sb + KA_A_OFF + (uint32_t)(term * KA_ATERM + row * 272 + c * 16),
                     src + (((size_t)(b << 11) + stok[nxt * 64 + row]) << 8) + (c << 3));
            }
            CP_COMMIT();
        }

        // ---- compute kh = 1 from buf1 ----
#pragma unroll
        for (int ks = 0; ks < 8; ++ks) {
            uint32_t ah[2][4], al[2][4], bh[4][2], bl[4][2], tmp[4];
#pragma unroll
            for (int m = 0; m < 2; ++m) {
                uint32_t ro = (uint32_t)((warpM * 32 + m * 16) * 272 + ks * 32);
                ldsm4(ah[m], a_ld_base + KA_ABUF + ro);
                ldsm4(al[m], a_ld_base + KA_ABUF + KA_ATERM + ro);
            }
#pragma unroll
            for (int nc = 0; nc < 2; ++nc) {
                uint32_t no = (uint32_t)(nc * 16 * 528 + 256 + ks * 32);
                ldsm4(tmp, b_ld_base + no);
                bh[2 * nc][0] = tmp[0]; bh[2 * nc + 1][0] = tmp[1];
                bh[2 * nc][1] = tmp[2]; bh[2 * nc + 1][1] = tmp[3];
                ldsm4(tmp, b_ld_base + 67584 + no);
                bl[2 * nc][0] = tmp[0]; bl[2 * nc + 1][0] = tmp[1];
                bl[2 * nc][1] = tmp[2]; bl[2 * nc + 1][1] = tmp[3];
            }
#pragma unroll
            for (int m = 0; m < 2; ++m)
#pragma unroll
                for (int n = 0; n < 4; ++n) mma16816(C[m][n], ah[m], bh[n]);
#pragma unroll
            for (int m = 0; m < 2; ++m)
#pragma unroll
                for (int n = 0; n < 4; ++n) mma16816(C[m][n], ah[m], bl[n]);
#pragma unroll
            for (int m = 0; m < 2; ++m)
#pragma unroll
                for (int n = 0; n < 4; ++n) mma16816(C[m][n], al[m], bh[n]);
        }

        // ---- epilogue: a-weighted lrelu accumulate ----
#pragma unroll
        for (int m = 0; m < 2; ++m) {
            float a0 = sa[cur * 64 + warpM * 32 + m * 16 + gid];
            float a1 = sa[cur * 64 + warpM * 32 + m * 16 + gid + 8];
#pragma unroll
            for (int n = 0; n < 4; ++n) {
                colacc[n][0] += a0 * lrelu(C[m][n][0] + ban0[n])
                              + a1 * lrelu(C[m][n][2] + ban0[n]);
                colacc[n][1] += a0 * lrelu(C[m][n][1] + ban1[n])
                              + a1 * lrelu(C[m][n][3] + ban1[n]);
            }
        }
    }

    // reduce over gid lanes, two warpM warps combine via atomics
#pragma unroll
    for (int n = 0; n < 4; ++n)
#pragma unroll
        for (int j = 0; j < 2; ++j) {
            float v = colacc[n][j];
            v += __shfl_xor_sync(0xffffffffu, v, 4);
            v += __shfl_xor_sync(0xffffffffu, v, 8);
            v += __shfl_xor_sync(0xffffffffu, v, 16);
            colacc[n][j] = v;
        }
    if (lane < 4) {
#pragma unroll
        for (int n = 0; n < 4; ++n) {
            int c0 = colbase + warpN * 32 + n * 8 + 2 * lane;
            atomicAdd(&out_u[b * DU + c0],     colacc[n][0]);
            atomicAdd(&out_u[b * DU + c0 + 1], colacc[n][1]);
        }
    }
}

// ---------------- launch ----------------
extern "C" void kernel_launch(void* const* d_in, const int* in_sizes, int n_in,
                              void* d_out, int out_size) {
    const int*   q_seq = (const int*)d_in[0];
    const int*   r_seq = (const int*)d_in[1];
    const float* t_seq = (const float*)d_in[2];
    const float* mask  = (const float*)d_in[3];
    const float* q_tab = (const float*)d_in[4];
    const float* r_tab = (const float*)d_in[5];
    const float* vn    = (const float*)d_in[6];
    const float* Ws1   = (const float*)d_in[7];
    const float* bs1   = (const float*)d_in[8];
    const float* Ws2   = (const float*)d_in[9];
    const float* bs2   = (const float*)d_in[10];
    const float* Wa    = (const float*)d_in[11];
    const float* ba    = (const float*)d_in[12];

    float* out_u = (float*)d_out;            // (64, 1024)
    float* outA  = out_u + BATCH * DU;       // (64, 2048)

    k_setup<<<4, 1024>>>(Ws1, bs1, vn);
    k_prep<<<(DU * DMODEL + 255) / 256, 256>>>(Wa, out_u);

    k_emb<<<NTOK / 16, 256>>>(q_seq, r_seq, t_seq, q_tab, r_tab);

    size_t smemL = (size_t)(128 * 257 + 256 * 66) * sizeof(float) + 16;
    cudaFuncSetAttribute(k_logits, cudaFuncAttributeMaxDynamicSharedMemorySize, (int)smemL);
    k_logits<<<148, 512, smemL>>>(mask, Ws1, Ws2, bs2, outA);

    cudaFuncSetAttribute(k_agg_p, cudaFuncAttributeMaxDynamicSharedMemorySize, SMEM_AGG);
    k_agg_p<<<dim3(8, BATCH), 256, SMEM_AGG>>>(ba, out_u);
}

// round 6
// speedup vs baseline: 3.1836x; 1.0345x over previous
#include <cuda_runtime.h>
#include <cuda_bf16.h>
#include <math.h>
#include <stdint.h>

typedef unsigned long long ull;

#define BATCH 64
#define LSEQ  2048
#define DMODEL 256
#define DU 1024
#define HHID 128
#define NTOK (BATCH*LSEQ)
#define LTOK 128
#define LTILE (NTOK/LTOK)   // 1024

// ---------------- device scratch ----------------
__device__ __nv_bfloat16 g_hev_hi[(size_t)NTOK * DMODEL];
__device__ __nv_bfloat16 g_hev_lo[(size_t)NTOK * DMODEL];
__device__ __nv_bfloat16 g_Wa_hi[DU * DMODEL];
__device__ __nv_bfloat16 g_Wa_lo[DU * DMODEL];
__device__ float g_cvec[HHID];
__device__ float g_aval[NTOK];
__device__ int   g_active[NTOK];
__device__ int   g_count[BATCH];
__device__ int   g_tile;

// ---------------- helpers ----------------
__device__ __forceinline__ ull pk2(float v) {
    ull r; asm("mov.b64 %0, {%1, %1};" : "=l"(r) : "f"(v)); return r;
}
__device__ __forceinline__ float2 unpk(ull v) {
    float2 r; asm("mov.b64 {%0, %1}, %2;" : "=f"(r.x), "=f"(r.y) : "l"(v)); return r;
}
__device__ __forceinline__ ull fma2(ull a, ull b, ull c) {
    ull d; asm("fma.rn.f32x2 %0, %1, %2, %3;" : "=l"(d) : "l"(a), "l"(b), "l"(c)); return d;
}
__device__ __forceinline__ float lrelu(float x) { return x > 0.f ? x : 0.2f * x; }

__device__ __forceinline__ uint32_t smem_u32(const void* p) {
    uint32_t a;
    asm("{ .reg .u64 t; cvta.to.shared.u64 t, %1; cvt.u32.u64 %0, t; }" : "=r"(a) : "l"(p));
    return a;
}
__device__ __forceinline__ void mma16816(float* d, const uint32_t* a, const uint32_t* b) {
    asm volatile(
        "mma.sync.aligned.m16n8k16.row.col.f32.bf16.bf16.f32 "
        "{%0,%1,%2,%3}, {%4,%5,%6,%7}, {%8,%9}, {%0,%1,%2,%3};"
        : "+f"(d[0]), "+f"(d[1]), "+f"(d[2]), "+f"(d[3])
        : "r"(a[0]), "r"(a[1]), "r"(a[2]), "r"(a[3]), "r"(b[0]), "r"(b[1]));
}
__device__ __forceinline__ void ldsm4(uint32_t* r, uint32_t addr) {
    asm volatile("ldmatrix.sync.aligned.m8n8.x4.shared.b16 {%0,%1,%2,%3}, [%4];"
        : "=r"(r[0]), "=r"(r[1]), "=r"(r[2]), "=r"(r[3]) : "r"(addr));
}
__device__ __forceinline__ void cp16(uint32_t dst, const void* src) {
    asm volatile("cp.async.cg.shared.global [%0], [%1], 16;" :: "r"(dst), "l"(src));
}
#define CP_COMMIT() asm volatile("cp.async.commit_group;" ::: "memory")
#define CP_WAIT0()  asm volatile("cp.async.wait_group 0;" ::: "memory")

// ---------------- kernel 0a: constant head bias ----------------
__global__ void k_setup(const float* __restrict__ Ws1, const float* __restrict__ bs1,
                        const float* __restrict__ vn) {
    int h = blockIdx.x * (blockDim.x >> 5) + (threadIdx.x >> 5);
    int l = threadIdx.x & 31;
    if (h >= HHID) return;
    const float* row = Ws1 + (size_t)h * 512 + 256;
    float s = 0.f;
#pragma unroll
    for (int d = l; d < 256; d += 32) s += row[d] * vn[d];
#pragma unroll
    for (int off = 16; off; off >>= 1) s += __shfl_xor_sync(0xffffffffu, s, off);
    if (l == 0) g_cvec[h] = s + bs1[h];
}

// ---------------- kernel 0b: Wa -> bf16 hi/lo, zero outputs ----------------
__global__ void k_prep(const float* __restrict__ Wa, float* __restrict__ out_u) {
    int idx = blockIdx.x * blockDim.x + threadIdx.x;
    if (idx < DU * DMODEL) {
        float v = Wa[idx];
        __nv_bfloat16 hi = __float2bfloat16(v);
        __nv_bfloat16 lo = __float2bfloat16(v - __bfloat162float(hi));
        g_Wa_hi[idx] = hi;
        g_Wa_lo[idx] = lo;
    }
    if (idx < BATCH * DU) out_u[idx] = 0.f;
    if (idx < BATCH) g_count[idx] = 0;
    if (idx == 0) g_tile = 0;
}

// ---------------- kernel 1a: embedding + trig -> bf16 hi/lo ----------------
__global__ __launch_bounds__(256) void k_emb(
    const int* __restrict__ q_seq, const int* __restrict__ r_seq,
    const float* __restrict__ t_seq,
    const float* __restrict__ q_tab, const float* __restrict__ r_tab)
{
    __shared__ int sq[16], sr[16];
    __shared__ float st[16];
    const int tid = threadIdx.x;
    const int tok0 = blockIdx.x * 16;
    if (tid < 16) {
        sq[tid] = q_seq[tok0 + tid];
        sr[tid] = r_seq[tok0 + tid];
        st[tid] = t_seq[tok0 + tid];
    }
    __syncthreads();
    const int d = tid;
    const float ddf  = (float)(d & 127);
    const float freq = expf(ddf * (-9.2103403719761836f / 128.f));
    const bool is_sin = d < 128;
    __nv_bfloat16* ghi = g_hev_hi + (size_t)tok0 * 256 + d;
    __nv_bfloat16* glo = g_hev_lo + (size_t)tok0 * 256 + d;
#pragma unroll 4
    for (int t = 0; t < 16; ++t) {
        float arg = st[t] * freq;
        float tv  = is_sin ? sinf(arg) : cosf(arg);
        float val = q_tab[(size_t)sq[t] * 256 + d] + r_tab[sr[t] * 256 + d] + tv;
        __nv_bfloat16 hb = __float2bfloat16(val);
        ghi[(size_t)t * 256] = hb;
        glo[(size_t)t * 256] = __float2bfloat16(val - __bfloat162float(hb));
    }
}

// ---------------- kernel 1b: persistent fp32 logits, 128-token tiles ----------------
// smem: ws[128][257] (131584B) + hT[128 d][132] (67584B) + stile
#define HT_P 132
__global__ __launch_bounds__(512) void k_logits(
    const float* __restrict__ mask, const float* __restrict__ Ws1,
    const float* __restrict__ Ws2, const float* __restrict__ bs2,
    float* __restrict__ outA)
{
    extern __shared__ float sm[];
    float* ws  = sm;                        // 128*257
    float* hT  = ws + 128 * 257;            // 128*132 (one 128-d chunk)
    int*   stile = (int*)(hT + 128 * HT_P);

    const int tid = threadIdx.x;
    const int w   = tid >> 5;               // 0..15
    const int l   = tid & 31;

    for (int idx = tid; idx < 128 * 256; idx += 512) {
        int hh = idx >> 8, dd = idx & 255;
        ws[hh * 257 + dd] = Ws1[hh * 512 + dd];
    }

    float w2r[4], cr[4];
#pragma unroll
    for (int j = 0; j < 4; ++j) {
        w2r[j] = Ws2[l + 32 * j];
        cr[j]  = g_cvec[l + 32 * j];
    }
    const float b2v = bs2[0];

    // staging ids: tt = token-in-tile (0..127), dg -> 32-d group in chunk
    const int tt = tid & 127;
    const int dg = tid >> 7;                // 0..3

    const float* wp0 = ws + (l +  0) * 257;
    const float* wp1 = ws + (l + 32) * 257;
    const float* wp2 = ws + (l + 64) * 257;
    const float* wp3 = ws + (l + 96) * 257;
    const float* hbase = hT + (w << 3);

    if (tid == 0) *stile = atomicAdd(&g_tile, 1);
    __syncthreads();

    int tile = *stile;
    while (tile < LTILE) {
        const int tok0 = tile * LTOK;
        const int b    = tok0 >> 11;

        ull acc[4][4];
#pragma unroll
        for (int j = 0; j < 4; ++j)
#pragma unroll
            for (int p = 0; p < 4; ++p) acc[j][p] = 0ull;

#pragma unroll
        for (int chunk = 0; chunk < 2; ++chunk) {
            const int dbase = chunk * 128;
            // ---- stage hT chunk: 128 tokens x 128 d (f32 = hi + lo) ----
            {
                const __nv_bfloat16* ph = g_hev_hi + (size_t)(tok0 + tt) * 256 + dbase + dg * 32;
                const __nv_bfloat16* pl = g_hev_lo + (size_t)(tok0 + tt) * 256 + dbase + dg * 32;
#pragma unroll
                for (int c = 0; c < 4; ++c) {
                    uint4 vh = *(const uint4*)(ph + c * 8);
                    uint4 vl = *(const uint4*)(pl + c * 8);
                    const __nv_bfloat16* hh_ = (const __nv_bfloat16*)&vh;
                    const __nv_bfloat16* ll_ = (const __nv_bfloat16*)&vl;
#pragma unroll
                    for (int j = 0; j < 8; ++j)
                        hT[(dg * 32 + c * 8 + j) * HT_P + tt] =
                            __bfloat162float(hh_[j]) + __bfloat162float(ll_[j]);
                }
            }
            __syncthreads();

            // ---- fp32x2 GEMM over this d-chunk: warp w -> tokens [8w,8w+8) ----
#pragma unroll 4
            for (int d = 0; d < 128; ++d) {
                ull wv0 = pk2(wp0[dbase + d]);
                ull wv1 = pk2(wp1[dbase + d]);
                ull wv2 = pk2(wp2[dbase + d]);
                ull wv3 = pk2(wp3[dbase + d]);
                const ull* hp = (const ull*)(hbase + d * HT_P);
                ull h0 = hp[0], h1 = hp[1], h2 = hp[2], h3 = hp[3];
                acc[0][0] = fma2(h0, wv0, acc[0][0]);
                acc[1][0] = fma2(h0, wv1, acc[1][0]);
                acc[2][0] = fma2(h0, wv2, acc[2][0]);
                acc[3][0] = fma2(h0, wv3, acc[3][0]);
                acc[0][1] = fma2(h1, wv0, acc[0][1]);
                acc[1][1] = fma2(h1, wv1, acc[1][1]);
                acc[2][1] = fma2(h1, wv2, acc[2][1]);
                acc[3][1] = fma2(h1, wv3, acc[3][1]);
                acc[0][2] = fma2(h2, wv0, acc[0][2]);
                acc[1][2] = fma2(h2, wv1, acc[1][2]);
                acc[2][2] = fma2(h2, wv2, acc[2][2]);
                acc[3][2] = fma2(h2, wv3, acc[3][2]);
                acc[0][3] = fma2(h3, wv0, acc[0][3]);
                acc[1][3] = fma2(h3, wv1, acc[1][3]);
                acc[2][3] = fma2(h3, wv2, acc[2][3]);
                acc[3][3] = fma2(h3, wv3, acc[3][3]);
            }
            __syncthreads();
        }

        if (tid == 0) *stile = atomicAdd(&g_tile, 1);

        // ---- epilogue: logits + sigmoid + compaction ----
#pragma unroll
        for (int p = 0; p < 4; ++p) {
            float sx = 0.f, sy = 0.f;
#pragma unroll
            for (int j = 0; j < 4; ++j) {
                float2 v = unpk(acc[j][p]);
                sx += w2r[j] * lrelu(v.x + cr[j]);
                sy += w2r[j] * lrelu(v.y + cr[j]);
            }
#pragma unroll
            for (int off = 16; off; off >>= 1) {
                sx += __shfl_xor_sync(0xffffffffu, sx, off);
                sy += __shfl_xor_sync(0xffffffffu, sy, off);
            }
            if (l == 0) {
                int t0 = tok0 + (w << 3) + 2 * p;
#pragma unroll
                for (int k = 0; k < 2; ++k) {
                    int   t     = t0 + k;
                    float logit = (k ? sy : sx) + b2v;
                    float a = mask[t] / (1.f + expf(-logit * 100.f));
                    outA[t]   = a;
                    g_aval[t] = a;
                    if (a > 1e-10f) {
                        int slot = atomicAdd(&g_count[b], 1);
                        g_active[b * LSEQ + slot] = t & (LSEQ - 1);
                    }
                }
            }
        }
        __syncthreads();
        tile = *stile;
    }
}

// ---------------- kernel 2: pipelined HMMA aggregator (unchanged from R5) ----------------
#define KA_B_OFF   0
#define KA_A_OFF   135168
#define KA_ABUF    34816
#define KA_ATERM   17408
#define KA_SA_OFF  204800
#define KA_STOK_OFF 205312
#define SMEM_AGG   205824

__global__ __launch_bounds__(256, 1) void k_agg_p(const float* __restrict__ ba,
                                                  float* __restrict__ out_u)
{
    extern __shared__ char smem[];
    const uint32_t sb = smem_u32(smem);
    const int tid  = threadIdx.x;
    const int wid  = tid >> 5;
    const int lane = tid & 31;
    const int gid  = lane >> 2;
    const int b    = blockIdx.y;
    const int colbase = blockIdx.x * 128;
    const int warpM = wid >> 2;
    const int warpN = wid & 3;

    float* sa   = (float*)(smem + KA_SA_OFF);
    int*   stok = (int*)(smem + KA_STOK_OFF);

    for (int i = tid; i < 8192; i += 256) {
        int term = i >> 12;
        int r = (i >> 5) & 127;
        int c = i & 31;
        const __nv_bfloat16* src = term ? g_Wa_lo : g_Wa_hi;
        uint4 v = ((const uint4*)(src + ((size_t)(colbase + r) << 8)))[c];
        *(uint4*)(smem + KA_B_OFF + term * 67584 + r * 528 + c * 16) = v;
    }

    const int cnt = g_count[b];
    const int ntile = (cnt + 63) >> 6;

    float colacc[4][2];
#pragma unroll
    for (int n = 0; n < 4; ++n) { colacc[n][0] = 0.f; colacc[n][1] = 0.f; }
    float ban0[4], ban1[4];
#pragma unroll
    for (int n = 0; n < 4; ++n) {
        int c0 = colbase + warpN * 32 + n * 8 + 2 * (lane & 3);
        ban0[n] = ba[c0];
        ban1[n] = ba[c0 + 1];
    }

    if (tid < 64 && ntile > 0) {
        int tok = (tid < cnt) ? g_active[(b << 11) + tid] : 0;
        stok[tid] = tok;
        sa[tid]   = (tid < cnt) ? g_aval[(b << 11) + tok] : 0.f;
    }
    __syncthreads();

    const uint32_t a_ld_base = sb + KA_A_OFF
        + (uint32_t)((lane & 15) * 272 + (lane >> 4) * 16);
    const uint32_t b_ld_base = sb + KA_B_OFF
        + (uint32_t)((warpN * 32 + (lane & 15)) * 528 + (lane >> 4) * 16);

    if (ntile > 0) {
#pragma unroll
        for (int i = 0; i < 8; ++i) {
            int idx = tid + i * 256;
            int term = idx >> 10;
            int row  = (idx >> 4) & 63;
            int c    = idx & 15;
            const __nv_bfloat16* src = term ? g_hev_lo : g_hev_hi;
            cp16(sb + KA_A_OFF + (uint32_t)(term * KA_ATERM + row * 272 + c * 16),
                 src + (((size_t)(b << 11) + stok[row]) << 8) + (c << 3));
        }
        CP_COMMIT();
    }

    int cur = 0;
    for (int t = 0; t < ntile; ++t, cur ^= 1) {
        const int nxt = cur ^ 1;
        if (tid < 64 && t + 1 < ntile) {
            int slot = ((t + 1) << 6) + tid;
            int tok = (slot < cnt) ? g_active[(b << 11) + slot] : 0;
            stok[nxt * 64 + tid] = tok;
            sa[nxt * 64 + tid]   = (slot < cnt) ? g_aval[(b << 11) + tok] : 0.f;
        }
        CP_WAIT0();
        __syncthreads();

#pragma unroll
        for (int i = 0; i < 8; ++i) {
            int idx = tid + i * 256;
            int term = idx >> 10;
            int row  = (idx >> 4) & 63;
            int c    = idx & 15;
            const __nv_bfloat16* src = term ? g_hev_lo : g_hev_hi;
            cp16(sb + KA_A_OFF + KA_ABUF
                     + (uint32_t)(term * KA_ATERM + row * 272 + c * 16),
                 src + (((size_t)(b << 11) + stok[cur * 64 + row]) << 8) + 128 + (c << 3));
        }
        CP_COMMIT();

        float C[2][4][4];
#pragma unroll
        for (int m = 0; m < 2; ++m)
#pragma unroll
            for (int n = 0; n < 4; ++n)
#pragma unroll
                for (int k = 0; k < 4; ++k) C[m][n][k] = 0.f;

#pragma unroll
        for (int ks = 0; ks < 8; ++ks) {
            uint32_t ah[2][4], al[2][4], bh[4][2], bl[4][2], tmp[4];
#pragma unroll
            for (int m = 0; m < 2; ++m) {
                uint32_t ro = (uint32_t)((warpM * 32 + m * 16) * 272 + ks * 32);
                ldsm4(ah[m], a_ld_base + ro);
                ldsm4(al[m], a_ld_base + KA_ATERM + ro);
            }
#pragma unroll
            for (int nc = 0; nc < 2; ++nc) {
                uint32_t no = (uint32_t)(nc * 16 * 528 + ks * 32);
                ldsm4(tmp, b_ld_base + no);
                bh[2 * nc][0] = tmp[0]; bh[2 * nc + 1][0] = tmp[1];
                bh[2 * nc][1] = tmp[2]; bh[2 * nc + 1][1] = tmp[3];
                ldsm4(tmp, b_ld_base + 67584 + no);
                bl[2 * nc][0] = tmp[0]; bl[2 * nc + 1][0] = tmp[1];
                bl[2 * nc][1] = tmp[2]; bl[2 * nc + 1][1] = tmp[3];
            }
#pragma unroll
            for (int m = 0; m < 2; ++m)
#pragma unroll
                for (int n = 0; n < 4; ++n) mma16816(C[m][n], ah[m], bh[n]);
#pragma unroll
            for (int m = 0; m < 2; ++m)
#pragma unroll
                for (int n = 0; n < 4; ++n) mma16816(C[m][n], ah[m], bl[n]);
#pragma unroll
            for (int m = 0; m < 2; ++m)
#pragma unroll
                for (int n = 0; n < 4; ++n) mma16816(C[m][n], al[m], bh[n]);
        }

        CP_WAIT0();
        __syncthreads();

        if (t + 1 < ntile) {
#pragma unroll
            for (int i = 0; i < 8; ++i) {
                int idx = tid + i * 256;
                int term = idx >> 10;
                int row  = (idx >> 4) & 63;
                int c    = idx & 15;
                const __nv_bfloat16* src = term ? g_hev_lo : g_hev_hi;
                cp16(sb + KA_A_OFF + (uint32_t)(term * KA_ATERM + row * 272 + c * 16),
                     src + (((size_t)(b << 11) + stok[nxt * 64 + row]) << 8) + (c << 3));
            }
            CP_COMMIT();
        }

#pragma unroll
        for (int ks = 0; ks < 8; ++ks) {
            uint32_t ah[2][4], al[2][4], bh[4][2], bl[4][2], tmp[4];
#pragma unroll
            for (int m = 0; m < 2; ++m) {
                uint32_t ro = (uint32_t)((warpM * 32 + m * 16) * 272 + ks * 32);
                ldsm4(ah[m], a_ld_base + KA_ABUF + ro);
                ldsm4(al[m], a_ld_base + KA_ABUF + KA_ATERM + ro);
            }
#pragma unroll
            for (int nc = 0; nc < 2; ++nc) {
                uint32_t no = (uint32_t)(nc * 16 * 528 + 256 + ks * 32);
                ldsm4(tmp, b_ld_base + no);
                bh[2 * nc][0] = tmp[0]; bh[2 * nc + 1][0] = tmp[1];
                bh[2 * nc][1] = tmp[2]; bh[2 * nc + 1][1] = tmp[3];
                ldsm4(tmp, b_ld_base + 67584 + no);
                bl[2 * nc][0] = tmp[0]; bl[2 * nc + 1][0] = tmp[1];
                bl[2 * nc][1] = tmp[2]; bl[2 * nc + 1][1] = tmp[3];
            }
#pragma unroll
            for (int m = 0; m < 2; ++m)
#pragma unroll
                for (int n = 0; n < 4; ++n) mma16816(C[m][n], ah[m], bh[n]);
#pragma unroll
            for (int m = 0; m < 2; ++m)
#pragma unroll
                for (int n = 0; n < 4; ++n) mma16816(C[m][n], ah[m], bl[n]);
#pragma unroll
            for (int m = 0; m < 2; ++m)
#pragma unroll
                for (int n = 0; n < 4; ++n) mma16816(C[m][n], al[m], bh[n]);
        }

#pragma unroll
        for (int m = 0; m < 2; ++m) {
            float a0 = sa[cur * 64 + warpM * 32 + m * 16 + gid];
            float a1 = sa[cur * 64 + warpM * 32 + m * 16 + gid + 8];
#pragma unroll
            for (int n = 0; n < 4; ++n) {
                colacc[n][0] += a0 * lrelu(C[m][n][0] + ban0[n])
                              + a1 * lrelu(C[m][n][2] + ban0[n]);
                colacc[n][1] += a0 * lrelu(C[m][n][1] + ban1[n])
                              + a1 * lrelu(C[m][n][3] + ban1[n]);
            }
        }
    }

#pragma unroll
    for (int n = 0; n < 4; ++n)
#pragma unroll
        for (int j = 0; j < 2; ++j) {
            float v = colacc[n][j];
            v += __shfl_xor_sync(0xffffffffu, v, 4);
            v += __shfl_xor_sync(0xffffffffu, v, 8);
            v += __shfl_xor_sync(0xffffffffu, v, 16);
            colacc[n][j] = v;
        }
    if (lane < 4) {
#pragma unroll
        for (int n = 0; n < 4; ++n) {
            int c0 = colbase + warpN * 32 + n * 8 + 2 * lane;
            atomicAdd(&out_u[b * DU + c0],     colacc[n][0]);
            atomicAdd(&out_u[b * DU + c0 + 1], colacc[n][1]);
        }
    }
}

// ---------------- launch ----------------
extern "C" void kernel_launch(void* const* d_in, const int* in_sizes, int n_in,
                              void* d_out, int out_size) {
    const int*   q_seq = (const int*)d_in[0];
    const int*   r_seq = (const int*)d_in[1];
    const float* t_seq = (const float*)d_in[2];
    const float* mask  = (const float*)d_in[3];
    const float* q_tab = (const float*)d_in[4];
    const float* r_tab = (const float*)d_in[5];
    const float* vn    = (const float*)d_in[6];
    const float* Ws1   = (const float*)d_in[7];
    const float* bs1   = (const float*)d_in[8];
    const float* Ws2   = (const float*)d_in[9];
    const float* bs2   = (const float*)d_in[10];
    const float* Wa    = (const float*)d_in[11];
    const float* ba    = (const float*)d_in[12];

    float* out_u = (float*)d_out;            // (64, 1024)
    float* outA  = out_u + BATCH * DU;       // (64, 2048)

    k_setup<<<4, 1024>>>(Ws1, bs1, vn);
    k_prep<<<(DU * DMODEL + 255) / 256, 256>>>(Wa, out_u);

    k_emb<<<NTOK / 16, 256>>>(q_seq, r_seq, t_seq, q_tab, r_tab);

    size_t smemL = (size_t)(128 * 257 + 128 * HT_P) * sizeof(float) + 16;
    cudaFuncSetAttribute(k_logits, cudaFuncAttributeMaxDynamicSharedMemorySize, (int)smemL);
    k_logits<<<148, 512, smemL>>>(mask, Ws1, Ws2, bs2, outA);

    cudaFuncSetAttribute(k_agg_p, cudaFuncAttributeMaxDynamicSharedMemorySize, SMEM_AGG);
    k_agg_p<<<dim3(8, BATCH), 256, SMEM_AGG>>>(ba, out_u);
}

// round 7
// speedup vs baseline: 4.1153x; 1.2927x over previous
#include <cuda_runtime.h>
#include <cuda_bf16.h>
#include <math.h>
#include <stdint.h>

typedef unsigned long long ull;

#define BATCH 64
#define LSEQ  2048
#define DMODEL 256
#define DU 1024
#define HHID 128
#define NTOK (BATCH*LSEQ)
#define LTOK 128
#define LTILE (NTOK/LTOK)   // 1024

// ---------------- device scratch ----------------
__device__ __nv_bfloat16 g_hev_hi[(size_t)NTOK * DMODEL];
__device__ __nv_bfloat16 g_hev_lo[(size_t)NTOK * DMODEL];
__device__ __nv_bfloat16 g_Wa_hi[DU * DMODEL];
__device__ __nv_bfloat16 g_Wa_lo[DU * DMODEL];
__device__ __nv_bfloat16 g_W1_hi[HHID * DMODEL];
__device__ __nv_bfloat16 g_W1_lo[HHID * DMODEL];
__device__ float g_cvec[HHID];
__device__ float g_aval[NTOK];
__device__ int   g_active[NTOK];
__device__ int   g_count[BATCH];
__device__ int   g_tile;

// ---------------- helpers ----------------
__device__ __forceinline__ float lrelu(float x) { return x > 0.f ? x : 0.2f * x; }

__device__ __forceinline__ uint32_t smem_u32(const void* p) {
    uint32_t a;
    asm("{ .reg .u64 t; cvta.to.shared.u64 t, %1; cvt.u32.u64 %0, t; }" : "=r"(a) : "l"(p));
    return a;
}
__device__ __forceinline__ void mma16816(float* d, const uint32_t* a, const uint32_t* b) {
    asm volatile(
        "mma.sync.aligned.m16n8k16.row.col.f32.bf16.bf16.f32 "
        "{%0,%1,%2,%3}, {%4,%5,%6,%7}, {%8,%9}, {%0,%1,%2,%3};"
        : "+f"(d[0]), "+f"(d[1]), "+f"(d[2]), "+f"(d[3])
        : "r"(a[0]), "r"(a[1]), "r"(a[2]), "r"(a[3]), "r"(b[0]), "r"(b[1]));
}
__device__ __forceinline__ void ldsm4(uint32_t* r, uint32_t addr) {
    asm volatile("ldmatrix.sync.aligned.m8n8.x4.shared.b16 {%0,%1,%2,%3}, [%4];"
        : "=r"(r[0]), "=r"(r[1]), "=r"(r[2]), "=r"(r[3]) : "r"(addr));
}
__device__ __forceinline__ void cp16(uint32_t dst, const void* src) {
    asm volatile("cp.async.cg.shared.global [%0], [%1], 16;" :: "r"(dst), "l"(src));
}
#define CP_COMMIT() asm volatile("cp.async.commit_group;" ::: "memory")
#define CP_WAIT0()  asm volatile("cp.async.wait_group 0;" ::: "memory")

// ---------------- kernel 0a: constant head bias ----------------
__global__ void k_setup(const float* __restrict__ Ws1, const float* __restrict__ bs1,
                        const float* __restrict__ vn) {
    int h = blockIdx.x * (blockDim.x >> 5) + (threadIdx.x >> 5);
    int l = threadIdx.x & 31;
    if (h >= HHID) return;
    const float* row = Ws1 + (size_t)h * 512 + 256;
    float s = 0.f;
#pragma unroll
    for (int d = l; d < 256; d += 32) s += row[d] * vn[d];
#pragma unroll
    for (int off = 16; off; off >>= 1) s += __shfl_xor_sync(0xffffffffu, s, off);
    if (l == 0) g_cvec[h] = s + bs1[h];
}

// ---------------- kernel 0b: weights -> bf16 hi/lo, zero outputs ----------------
__global__ void k_prep(const float* __restrict__ Wa, const float* __restrict__ Ws1,
                       float* __restrict__ out_u) {
    int idx = blockIdx.x * blockDim.x + threadIdx.x;
    if (idx < DU * DMODEL) {
        float v = Wa[idx];
        __nv_bfloat16 hi = __float2bfloat16(v);
        __nv_bfloat16 lo = __float2bfloat16(v - __bfloat162float(hi));
        g_Wa_hi[idx] = hi;
        g_Wa_lo[idx] = lo;
    }
    if (idx < HHID * DMODEL) {
        int h = idx >> 8, d = idx & 255;
        float v = Ws1[h * 512 + d];
        __nv_bfloat16 hi = __float2bfloat16(v);
        __nv_bfloat16 lo = __float2bfloat16(v - __bfloat162float(hi));
        g_W1_hi[idx] = hi;
        g_W1_lo[idx] = lo;
    }
    if (idx < BATCH * DU) out_u[idx] = 0.f;
    if (idx < BATCH) g_count[idx] = 0;
    if (idx == 0) g_tile = 0;
}

// ---------------- kernel 1a: embedding + trig -> bf16 hi/lo ----------------
__global__ __launch_bounds__(256) void k_emb(
    const int* __restrict__ q_seq, const int* __restrict__ r_seq,
    const float* __restrict__ t_seq,
    const float* __restrict__ q_tab, const float* __restrict__ r_tab)
{
    __shared__ int sq[16], sr[16];
    __shared__ float st[16];
    const int tid = threadIdx.x;
    const int tok0 = blockIdx.x * 16;
    if (tid < 16) {
        sq[tid] = q_seq[tok0 + tid];
        sr[tid] = r_seq[tok0 + tid];
        st[tid] = t_seq[tok0 + tid];
    }
    __syncthreads();
    const int d = tid;
    const float ddf  = (float)(d & 127);
    const float freq = expf(ddf * (-9.2103403719761836f / 128.f));
    const bool is_sin = d < 128;
    __nv_bfloat16* ghi = g_hev_hi + (size_t)tok0 * 256 + d;
    __nv_bfloat16* glo = g_hev_lo + (size_t)tok0 * 256 + d;
#pragma unroll 4
    for (int t = 0; t < 16; ++t) {
        float arg = st[t] * freq;
        float tv  = is_sin ? sinf(arg) : cosf(arg);
        float val = q_tab[(size_t)sq[t] * 256 + d] + r_tab[sr[t] * 256 + d] + tv;
        __nv_bfloat16 hb = __float2bfloat16(val);
        ghi[(size_t)t * 256] = hb;
        glo[(size_t)t * 256] = __float2bfloat16(val - __bfloat162float(hb));
    }
}

// ---------------- kernel 1b: HMMA logits + compaction ----------------
// persistent 148 blocks x 256 thr. GEMM: Ws1a[128h x 256d] x h[256d x 128tok].
// smem: sW[2 terms][128 h][528B] @0 = 135168
//       sH[2 terms][128 tok][272B] @135168 = 69632
//       slog[2][128] @204800, stile @205824
#define LW_OFF   0
#define LW_TERM  67584
#define LH_OFF   135168
#define LH_TERM  34816
#define LSLOG    204800
#define LSTILE   205824
#define SMEM_LG  205952

__global__ __launch_bounds__(256, 1) void k_logits_mma(
    const float* __restrict__ mask, const float* __restrict__ Ws2,
    const float* __restrict__ bs2, float* __restrict__ outA)
{
    extern __shared__ char smem[];
    const uint32_t sb = smem_u32(smem);
    const int tid  = threadIdx.x;
    const int wid  = tid >> 5;
    const int lane = tid & 31;
    const int gid  = lane >> 2;
    const int warpM = wid >> 2;       // 0/1 -> h halves
    const int warpN = wid & 3;        // 0..3 -> 32-token groups

    float* slog  = (float*)(smem + LSLOG);
    int*   stile = (int*)(smem + LSTILE);

    // stage Ws1a hi/lo once per block
    for (int i = tid; i < 8192; i += 256) {
        int term = i >> 12;
        int r = (i >> 5) & 127;
        int c = i & 31;
        const __nv_bfloat16* src = term ? g_W1_lo : g_W1_hi;
        uint4 v = ((const uint4*)(src + ((size_t)r << 8)))[c];
        *(uint4*)(smem + LW_OFF + term * LW_TERM + r * 528 + c * 16) = v;
    }

    // per-thread epilogue constants
    float wc[4][2], cv[4][2];
#pragma unroll
    for (int m = 0; m < 4; ++m) {
        int h0 = warpM * 64 + m * 16 + gid;
        wc[m][0] = Ws2[h0];     wc[m][1] = Ws2[h0 + 8];
        cv[m][0] = g_cvec[h0];  cv[m][1] = g_cvec[h0 + 8];
    }
    const float b2v = bs2[0];

    // A-staging ids
    const int st_term = tid >> 7;
    const int st_row  = tid & 127;

    // ldsm bases
    const uint32_t w_ld = sb + LW_OFF + (uint32_t)((lane & 15) * 528 + (lane >> 4) * 16);
    const uint32_t h_ld = sb + LH_OFF +
        (uint32_t)((warpN * 32 + (lane & 15)) * 272 + (lane >> 4) * 16);

    if (tid == 0) *stile = atomicAdd(&g_tile, 1);
    __syncthreads();
    int tile = *stile;

    uint4 RA[16];
    if (tile < LTILE) {
        const uint4* p = (const uint4*)((st_term ? g_hev_lo : g_hev_hi)
                        + ((size_t)(tile * LTOK + st_row) << 8));
#pragma unroll
        for (int c = 0; c < 16; ++c) RA[c] = p[c];
    }

    while (tile < LTILE) {
        const int tok0 = tile * LTOK;
        const int b    = tok0 >> 11;

        // STS kh0
        {
            char* dst = smem + LH_OFF + st_term * LH_TERM + st_row * 272;
#pragma unroll
            for (int c = 0; c < 16; ++c) *(uint4*)(dst + c * 16) = RA[c];
        }
        __syncthreads();

        // LDG kh1 (overlaps GEMM kh0)
        {
            const uint4* p = (const uint4*)((st_term ? g_hev_lo : g_hev_hi)
                            + ((size_t)(tok0 + st_row) << 8) + 128);
#pragma unroll
            for (int c = 0; c < 16; ++c) RA[c] = p[c];
        }

        float C[4][4][4];
#pragma unroll
        for (int m = 0; m < 4; ++m)
#pragma unroll
            for (int n = 0; n < 4; ++n)
#pragma unroll
                for (int k = 0; k < 4; ++k) C[m][n][k] = 0.f;

        // ---- GEMM kh0 ----
#pragma unroll
        for (int ks = 0; ks < 8; ++ks) {
            uint32_t ah[4][4], al[4][4], bh[4][2], bl[4][2], tmp[4];
#pragma unroll
            for (int m = 0; m < 4; ++m) {
                uint32_t ro = (uint32_t)((warpM * 64 + m * 16) * 528 + ks * 32);
                ldsm4(ah[m], w_ld + ro);
                ldsm4(al[m], w_ld + LW_TERM + ro);
            }
#pragma unroll
            for (int nc = 0; nc < 2; ++nc) {
                uint32_t no = (uint32_t)(nc * 16 * 272 + ks * 32);
                ldsm4(tmp, h_ld + no);
                bh[2*nc][0] = tmp[0]; bh[2*nc+1][0] = tmp[1];
                bh[2*nc][1] = tmp[2]; bh[2*nc+1][1] = tmp[3];
                ldsm4(tmp, h_ld + LH_TERM + no);
                bl[2*nc][0] = tmp[0]; bl[2*nc+1][0] = tmp[1];
                bl[2*nc][1] = tmp[2]; bl[2*nc+1][1] = tmp[3];
            }
#pragma unroll
            for (int m = 0; m < 4; ++m)
#pragma unroll
                for (int n = 0; n < 4; ++n) mma16816(C[m][n], ah[m], bh[n]);
#pragma unroll
            for (int m = 0; m < 4; ++m)
#pragma unroll
                for (int n = 0; n < 4; ++n) mma16816(C[m][n], ah[m], bl[n]);
#pragma unroll
            for (int m = 0; m < 4; ++m)
#pragma unroll
                for (int n = 0; n < 4; ++n) mma16816(C[m][n], al[m], bh[n]);
        }
        __syncthreads();

        // STS kh1
        {
            char* dst = smem + LH_OFF + st_term * LH_TERM + st_row * 272;
#pragma unroll
            for (int c = 0; c < 16; ++c) *(uint4*)(dst + c * 16) = RA[c];
        }
        if (tid == 0) *stile = atomicAdd(&g_tile, 1);
        __syncthreads();

        // ---- GEMM kh1 ----
#pragma unroll
        for (int ks = 0; ks < 8; ++ks) {
            uint32_t ah[4][4], al[4][4], bh[4][2], bl[4][2], tmp[4];
#pragma unroll
            for (int m = 0; m < 4; ++m) {
                uint32_t ro = (uint32_t)((warpM * 64 + m * 16) * 528 + (8 + ks) * 32);
                ldsm4(ah[m], w_ld + ro);
                ldsm4(al[m], w_ld + LW_TERM + ro);
            }
#pragma unroll
            for (int nc = 0; nc < 2; ++nc) {
                uint32_t no = (uint32_t)(nc * 16 * 272 + ks * 32);
                ldsm4(tmp, h_ld + no);
                bh[2*nc][0] = tmp[0]; bh[2*nc+1][0] = tmp[1];
                bh[2*nc][1] = tmp[2]; bh[2*nc+1][1] = tmp[3];
                ldsm4(tmp, h_ld + LH_TERM + no);
                bl[2*nc][0] = tmp[0]; bl[2*nc+1][0] = tmp[1];
                bl[2*nc][1] = tmp[2]; bl[2*nc+1][1] = tmp[3];
            }
#pragma unroll
            for (int m = 0; m < 4; ++m)
#pragma unroll
                for (int n = 0; n < 4; ++n) mma16816(C[m][n], ah[m], bh[n]);
#pragma unroll
            for (int m = 0; m < 4; ++m)
#pragma unroll
                for (int n = 0; n < 4; ++n) mma16816(C[m][n], ah[m], bl[n]);
#pragma unroll
            for (int m = 0; m < 4; ++m)
#pragma unroll
                for (int n = 0; n < 4; ++n) mma16816(C[m][n], al[m], bh[n]);
        }

        const int nt = *stile;
        // LDG next tile kh0 (overlaps epilogue)
        if (nt < LTILE) {
            const uint4* p = (const uint4*)((st_term ? g_hev_lo : g_hev_hi)
                            + ((size_t)(nt * LTOK + st_row) << 8));
#pragma unroll
            for (int c = 0; c < 16; ++c) RA[c] = p[c];
        }

        // ---- epilogue: hdn -> ws2-weighted token partials ----
        {
            float tsum[4][2];
#pragma unroll
            for (int n = 0; n < 4; ++n) { tsum[n][0] = 0.f; tsum[n][1] = 0.f; }
#pragma unroll
            for (int m = 0; m < 4; ++m)
#pragma unroll
                for (int n = 0; n < 4; ++n) {
                    tsum[n][0] += wc[m][0] * lrelu(C[m][n][0] + cv[m][0])
                                + wc[m][1] * lrelu(C[m][n][2] + cv[m][1]);
                    tsum[n][1] += wc[m][0] * lrelu(C[m][n][1] + cv[m][0])
                                + wc[m][1] * lrelu(C[m][n][3] + cv[m][1]);
                }
#pragma unroll
            for (int n = 0; n < 4; ++n)
#pragma unroll
                for (int k2 = 0; k2 < 2; ++k2) {
                    float v = tsum[n][k2];
                    v += __shfl_xor_sync(0xffffffffu, v, 4);
                    v += __shfl_xor_sync(0xffffffffu, v, 8);
                    v += __shfl_xor_sync(0xffffffffu, v, 16);
                    tsum[n][k2] = v;
                }
            if (lane < 4) {
#pragma unroll
                for (int n = 0; n < 4; ++n) {
                    int t = warpN * 32 + n * 8 + 2 * lane;
                    slog[warpM * 128 + t]     = tsum[n][0];
                    slog[warpM * 128 + t + 1] = tsum[n][1];
                }
            }
        }
        __syncthreads();

        // ---- sigmoid + compaction (4 warps) ----
        if (tid < 128) {
            float logit = slog[tid] + slog[128 + tid] + b2v;
            float a = mask[tok0 + tid] / (1.f + expf(-logit * 100.f));
            outA[tok0 + tid]   = a;
            g_aval[tok0 + tid] = a;
            bool act = a > 1e-10f;
            unsigned mb = __ballot_sync(0xffffffffu, act);
            int cntw = __popc(mb);
            int base = 0;
            if (lane == 0 && cntw) base = atomicAdd(&g_count[b], cntw);
            base = __shfl_sync(0xffffffffu, base, 0);
            if (act) {
                int slot = base + __popc(mb & ((1u << lane) - 1u));
                g_active[b * LSEQ + slot] = (tok0 & (LSEQ - 1)) + tid;
            }
        }
        tile = nt;
        __syncthreads();
    }
}

// ---------------- kernel 2: pipelined HMMA aggregator (unchanged) ----------------
#define KA_B_OFF   0
#define KA_A_OFF   135168
#define KA_ABUF    34816
#define KA_ATERM   17408
#define KA_SA_OFF  204800
#define KA_STOK_OFF 205312
#define SMEM_AGG   205824

__global__ __launch_bounds__(256, 1) void k_agg_p(const float* __restrict__ ba,
                                                  float* __restrict__ out_u)
{
    extern __shared__ char smem[];
    const uint32_t sb = smem_u32(smem);
    const int tid  = threadIdx.x;
    const int wid  = tid >> 5;
    const int lane = tid & 31;
    const int gid  = lane >> 2;
    const int b    = blockIdx.y;
    const int colbase = blockIdx.x * 128;
    const int warpM = wid >> 2;
    const int warpN = wid & 3;

    float* sa   = (float*)(smem + KA_SA_OFF);
    int*   stok = (int*)(smem + KA_STOK_OFF);

    for (int i = tid; i < 8192; i += 256) {
        int term = i >> 12;
        int r = (i >> 5) & 127;
        int c = i & 31;
        const __nv_bfloat16* src = term ? g_Wa_lo : g_Wa_hi;
        uint4 v = ((const uint4*)(src + ((size_t)(colbase + r) << 8)))[c];
        *(uint4*)(smem + KA_B_OFF + term * 67584 + r * 528 + c * 16) = v;
    }

    const int cnt = g_count[b];
    const int ntile = (cnt + 63) >> 6;

    float colacc[4][2];
#pragma unroll
    for (int n = 0; n < 4; ++n) { colacc[n][0] = 0.f; colacc[n][1] = 0.f; }
    float ban0[4], ban1[4];
#pragma unroll
    for (int n = 0; n < 4; ++n) {
        int c0 = colbase + warpN * 32 + n * 8 + 2 * (lane & 3);
        ban0[n] = ba[c0];
        ban1[n] = ba[c0 + 1];
    }

    if (tid < 64 && ntile > 0) {
        int tok = (tid < cnt) ? g_active[(b << 11) + tid] : 0;
        stok[tid] = tok;
        sa[tid]   = (tid < cnt) ? g_aval[(b << 11) + tok] : 0.f;
    }
    __syncthreads();

    const uint32_t a_ld_base = sb + KA_A_OFF
        + (uint32_t)((lane & 15) * 272 + (lane >> 4) * 16);
    const uint32_t b_ld_base = sb + KA_B_OFF
        + (uint32_t)((warpN * 32 + (lane & 15)) * 528 + (lane >> 4) * 16);

    if (ntile > 0) {
#pragma unroll
        for (int i = 0; i < 8; ++i) {
            int idx = tid + i * 256;
            int term = idx >> 10;
            int row  = (idx >> 4) & 63;
            int c    = idx & 15;
            const __nv_bfloat16* src = term ? g_hev_lo : g_hev_hi;
            cp16(sb + KA_A_OFF + (uint32_t)(term * KA_ATERM + row * 272 + c * 16),
                 src + (((size_t)(b << 11) + stok[row]) << 8) + (c << 3));
        }
        CP_COMMIT();
    }

    int cur = 0;
    for (int t = 0; t < ntile; ++t, cur ^= 1) {
        const int nxt = cur ^ 1;
        if (tid < 64 && t + 1 < ntile) {
            int slot = ((t + 1) << 6) + tid;
            int tok = (slot < cnt) ? g_active[(b << 11) + slot] : 0;
            stok[nxt * 64 + tid] = tok;
            sa[nxt * 64 + tid]   = (slot < cnt) ? g_aval[(b << 11) + tok] : 0.f;
        }
        CP_WAIT0();
        __syncthreads();

#pragma unroll
        for (int i = 0; i < 8; ++i) {
            int idx = tid + i * 256;
            int term = idx >> 10;
            int row  = (idx >> 4) & 63;
            int c    = idx & 15;
            const __nv_bfloat16* src = term ? g_hev_lo : g_hev_hi;
            cp16(sb + KA_A_OFF + KA_ABUF
                     + (uint32_t)(term * KA_ATERM + row * 272 + c * 16),
                 src + (((size_t)(b << 11) + stok[cur * 64 + row]) << 8) + 128 + (c << 3));
        }
        CP_COMMIT();

        float C[2][4][4];
#pragma unroll
        for (int m = 0; m < 2; ++m)
#pragma unroll
            for (int n = 0; n < 4; ++n)
#pragma unroll
                for (int k = 0; k < 4; ++k) C[m][n][k] = 0.f;

#pragma unroll
        for (int ks = 0; ks < 8; ++ks) {
            uint32_t ah[2][4], al[2][4], bh[4][2], bl[4][2], tmp[4];
#pragma unroll
            for (int m = 0; m < 2; ++m) {
                uint32_t ro = (uint32_t)((warpM * 32 + m * 16) * 272 + ks * 32);
                ldsm4(ah[m], a_ld_base + ro);
                ldsm4(al[m], a_ld_base + KA_ATERM + ro);
            }
#pragma unroll
            for (int nc = 0; nc < 2; ++nc) {
                uint32_t no = (uint32_t)(nc * 16 * 528 + ks * 32);
                ldsm4(tmp, b_ld_base + no);
                bh[2*nc][0] = tmp[0]; bh[2*nc+1][0] = tmp[1];
                bh[2*nc][1] = tmp[2]; bh[2*nc+1][1] = tmp[3];
                ldsm4(tmp, b_ld_base + 67584 + no);
                bl[2*nc][0] = tmp[0]; bl[2*nc+1][0] = tmp[1];
                bl[2*nc][1] = tmp[2]; bl[2*nc+1][1] = tmp[3];
            }
#pragma unroll
            for (int m = 0; m < 2; ++m)
#pragma unroll
                for (int n = 0; n < 4; ++n) mma16816(C[m][n], ah[m], bh[n]);
#pragma unroll
            for (int m = 0; m < 2; ++m)
#pragma unroll
                for (int n = 0; n < 4; ++n) mma16816(C[m][n], ah[m], bl[n]);
#pragma unroll
            for (int m = 0; m < 2; ++m)
#pragma unroll
                for (int n = 0; n < 4; ++n) mma16816(C[m][n], al[m], bh[n]);
        }

        CP_WAIT0();
        __syncthreads();

        if (t + 1 < ntile) {
#pragma unroll
            for (int i = 0; i < 8; ++i) {
                int idx = tid + i * 256;
                int term = idx >> 10;
                int row  = (idx >> 4) & 63;
                int c    = idx & 15;
                const __nv_bfloat16* src = term ? g_hev_lo : g_hev_hi;
                cp16(sb + KA_A_OFF + (uint32_t)(term * KA_ATERM + row * 272 + c * 16),
                     src + (((size_t)(b << 11) + stok[nxt * 64 + row]) << 8) + (c << 3));
            }
            CP_COMMIT();
        }

#pragma unroll
        for (int ks = 0; ks < 8; ++ks) {
            uint32_t ah[2][4], al[2][4], bh[4][2], bl[4][2], tmp[4];
#pragma unroll
            for (int m = 0; m < 2; ++m) {
                uint32_t ro = (uint32_t)((warpM * 32 + m * 16) * 272 + ks * 32);
                ldsm4(ah[m], a_ld_base + KA_ABUF + ro);
                ldsm4(al[m], a_ld_base + KA_ABUF + KA_ATERM + ro);
            }
#pragma unroll
            for (int nc = 0; nc < 2; ++nc) {
                uint32_t no = (uint32_t)(nc * 16 * 528 + 256 + ks * 32);
                ldsm4(tmp, b_ld_base + no);
                bh[2*nc][0] = tmp[0]; bh[2*nc+1][0] = tmp[1];
                bh[2*nc][1] = tmp[2]; bh[2*nc+1][1] = tmp[3];
                ldsm4(tmp, b_ld_base + 67584 + no);
                bl[2*nc][0] = tmp[0]; bl[2*nc+1][0] = tmp[1];
                bl[2*nc][1] = tmp[2]; bl[2*nc+1][1] = tmp[3];
            }
#pragma unroll
            for (int m = 0; m < 2; ++m)
#pragma unroll
                for (int n = 0; n < 4; ++n) mma16816(C[m][n], ah[m], bh[n]);
#pragma unroll
            for (int m = 0; m < 2; ++m)
#pragma unroll
                for (int n = 0; n < 4; ++n) mma16816(C[m][n], ah[m], bl[n]);
#pragma unroll
            for (int m = 0; m < 2; ++m)
#pragma unroll
                for (int n = 0; n < 4; ++n) mma16816(C[m][n], al[m], bh[n]);
        }

#pragma unroll
        for (int m = 0; m < 2; ++m) {
            float a0 = sa[cur * 64 + warpM * 32 + m * 16 + gid];
            float a1 = sa[cur * 64 + warpM * 32 + m * 16 + gid + 8];
#pragma unroll
            for (int n = 0; n < 4; ++n) {
                colacc[n][0] += a0 * lrelu(C[m][n][0] + ban0[n])
                              + a1 * lrelu(C[m][n][2] + ban0[n]);
                colacc[n][1] += a0 * lrelu(C[m][n][1] + ban1[n])
                              + a1 * lrelu(C[m][n][3] + ban1[n]);
            }
        }
    }

#pragma unroll
    for (int n = 0; n < 4; ++n)
#pragma unroll
        for (int j = 0; j < 2; ++j) {
            float v = colacc[n][j];
            v += __shfl_xor_sync(0xffffffffu, v, 4);
            v += __shfl_xor_sync(0xffffffffu, v, 8);
            v += __shfl_xor_sync(0xffffffffu, v, 16);
            colacc[n][j] = v;
        }
    if (lane < 4) {
#pragma unroll
        for (int n = 0; n < 4; ++n) {
            int c0 = colbase + warpN * 32 + n * 8 + 2 * lane;
            atomicAdd(&out_u[b * DU + c0],     colacc[n][0]);
            atomicAdd(&out_u[b * DU + c0 + 1], colacc[n][1]);
        }
    }
}

// ---------------- launch ----------------
extern "C" void kernel_launch(void* const* d_in, const int* in_sizes, int n_in,
                              void* d_out, int out_size) {
    const int*   q_seq = (const int*)d_in[0];
    const int*   r_seq = (const int*)d_in[1];
    const float* t_seq = (const float*)d_in[2];
    const float* mask  = (const float*)d_in[3];
    const float* q_tab = (const float*)d_in[4];
    const float* r_tab = (const float*)d_in[5];
    const float* vn    = (const float*)d_in[6];
    const float* Ws1   = (const float*)d_in[7];
    const float* bs1   = (const float*)d_in[8];
    const float* Ws2   = (const float*)d_in[9];
    const float* bs2   = (const float*)d_in[10];
    const float* Wa    = (const float*)d_in[11];
    const float* ba    = (const float*)d_in[12];

    float* out_u = (float*)d_out;            // (64, 1024)
    float* outA  = out_u + BATCH * DU;       // (64, 2048)

    k_setup<<<4, 1024>>>(Ws1, bs1, vn);
    k_prep<<<(DU * DMODEL + 255) / 256, 256>>>(Wa, Ws1, out_u);

    k_emb<<<NTOK / 16, 256>>>(q_seq, r_seq, t_seq, q_tab, r_tab);

    cudaFuncSetAttribute(k_logits_mma, cudaFuncAttributeMaxDynamicSharedMemorySize, SMEM_LG);
    k_logits_mma<<<148, 256, SMEM_LG>>>(mask, Ws2, bs2, outA);

    cudaFuncSetAttribute(k_agg_p, cudaFuncAttributeMaxDynamicSharedMemorySize, SMEM_AGG);
    k_agg_p<<<dim3(8, BATCH), 256, SMEM_AGG>>>(ba, out_u);
}